// round 11
// baseline (speedup 1.0000x reference)
#include <cuda_runtime.h>
#include <cuda_fp16.h>

#define N_NODES 50000
#define D 128
#define E_MAX 800000

typedef unsigned long long ull;

// ---------------- device scratch (no allocation allowed) ----------------
__device__ float  g_y[(size_t)N_NODES * D];   // gather outputs (fp32 activations)
__device__ __half g_z[(size_t)N_NODES * D];   // GEMM outputs (fp16, gathered)
__device__ int    g_is64;
__device__ int    g_src[E_MAX];
__device__ int    g_dst[E_MAX];
__device__ int    g_perm[E_MAX];              // CSR: src ids grouped by dst
__device__ int    g_deg[N_NODES];
__device__ int    g_off[N_NODES];
__device__ int    g_cur[N_NODES];
__device__ int    g_part[256];                // lookback partials (flag-bit packed)

// ---------------- f32x2 packed helpers ----------------
__device__ __forceinline__ ull pack2(float a, float b) {
    ull r;
    asm("mov.b64 %0, {%1, %2};" : "=l"(r) : "f"(a), "f"(b));
    return r;
}
__device__ __forceinline__ ull add2(ull a, ull b) {
    ull r;
    asm("add.rn.f32x2 %0, %1, %2;" : "=l"(r) : "l"(a), "l"(b));
    return r;
}
__device__ __forceinline__ float2 unpack2(ull v) {
    float2 r;
    asm("mov.b64 {%0, %1}, %2;" : "=f"(r.x), "=f"(r.y) : "l"(v));
    return r;
}

// accumulate 8 halves (uint4) into 4 packed f32x2 accumulators
__device__ __forceinline__ void hacc(ull& a0, ull& a1, ull& a2, ull& a3, uint4 v) {
    float2 f0 = __half22float2(*(const __half2*)&v.x);
    float2 f1 = __half22float2(*(const __half2*)&v.y);
    float2 f2 = __half22float2(*(const __half2*)&v.z);
    float2 f3 = __half22float2(*(const __half2*)&v.w);
    a0 = add2(a0, pack2(f0.x, f0.y));
    a1 = add2(a1, pack2(f1.x, f1.y));
    a2 = add2(a2, pack2(f2.x, f2.y));
    a3 = add2(a3, pack2(f3.x, f3.y));
}

// ---------------- tf32 mma helpers ----------------
__device__ __forceinline__ unsigned to_tf32(float f) {
    unsigned r;
    asm("cvt.rna.tf32.f32 %0, %1;" : "=r"(r) : "f"(f));
    return r;
}
__device__ __forceinline__ void mma_tf32(float* c, unsigned a0, unsigned a1,
                                         unsigned a2, unsigned a3,
                                         unsigned b0, unsigned b1) {
    asm volatile(
        "mma.sync.aligned.m16n8k8.row.col.f32.tf32.tf32.f32 "
        "{%0,%1,%2,%3}, {%4,%5,%6,%7}, {%8,%9}, {%0,%1,%2,%3};"
        : "+f"(c[0]), "+f"(c[1]), "+f"(c[2]), "+f"(c[3])
        : "r"(a0), "r"(a1), "r"(a2), "r"(a3), "r"(b0), "r"(b1));
}

// ---------------- init: zero deg + lookback partials + dtype detect ---------
__global__ void init_kernel(const void* __restrict__ ei) {
    int i = blockIdx.x * blockDim.x + threadIdx.x;
    if (i < N_NODES) g_deg[i] = 0;
    if (i < 256) g_part[i] = 0;
    if (i == 0) {
        const long long* p = (const long long*)ei;
        int ok = 1;
        #pragma unroll
        for (int k = 0; k < 32; k++) {
            long long v = p[k];
            if (v < 0 || v >= N_NODES) ok = 0;
        }
        g_is64 = ok;
    }
}

// ---------------- CSR build: stage int32 + histogram --------------------
__global__ void convert_kernel(const void* __restrict__ ei, int E) {
    int i = blockIdx.x * blockDim.x + threadIdx.x;
    if (i >= E) return;
    int s, d;
    if (g_is64) {
        const long long* p = (const long long*)ei;
        s = (int)__ldg(p + i);
        d = (int)__ldg(p + E + i);
    } else {
        const int* p = (const int*)ei;
        s = __ldg(p + i);
        d = __ldg(p + E + i);
    }
    g_src[i] = s;
    g_dst[i] = d;
    atomicAdd(&g_deg[d], 1);
}

// fused exclusive scan (chained lookback across 196 co-resident blocks)
__global__ void scan_kernel(int n) {
    __shared__ int sh[8];
    __shared__ int sbase;
    int b = blockIdx.x, t = threadIdx.x, i = b * 256 + t;
    int v = (i < n) ? g_deg[i] : 0;
    int lane = t & 31, w = t >> 5;
    int x = v;
    #pragma unroll
    for (int o = 1; o < 32; o <<= 1) {
        int y = __shfl_up_sync(0xFFFFFFFFu, x, o);
        if (lane >= o) x += y;
    }
    if (lane == 31) sh[w] = x;
    __syncthreads();
    if (t < 8) {
        int s = sh[t];
        #pragma unroll
        for (int o = 1; o < 8; o <<= 1) {
            int y = __shfl_up_sync(0xFFu, s, o);
            if (t >= o) s += y;
        }
        sh[t] = s;
    }
    __syncthreads();
    int incl = x + (w ? sh[w - 1] : 0);

    if (t == 255) {                       // lookback: wait for predecessor
        int prev = 0;
        if (b > 0) {
            while (((prev = atomicAdd(&g_part[b - 1], 0)) & 0x80000000) == 0) ;
            prev &= 0x7FFFFFFF;
        }
        atomicExch(&g_part[b], (int)(0x80000000u | (unsigned)(prev + incl)));
        sbase = prev;
    }
    __syncthreads();
    if (i < n) {
        int o = incl - v + sbase;
        g_off[i] = o;
        g_cur[i] = o;
    }
}

__global__ void fill_kernel(int E) {
    int i = blockIdx.x * blockDim.x + threadIdx.x;
    if (i >= E) return;
    int d = g_dst[i];
    int p = atomicAdd(&g_cur[d], 1);
    g_perm[p] = g_src[i];
}

// ---------------- tf32 tensor-core GEMM: z = A @ W (fp16 out) ---------------
// A-chunk register-prefetched; W staged per-chunk (L2-hot).
template <int C>
__global__ __launch_bounds__(256, 2)
void gemm_tc_kernel(const float* __restrict__ A,
                    const float* __restrict__ W,
                    __half* __restrict__ out,
                    int N) {
    constexpr int BM = 128;
    constexpr int BK = 32;
    constexpr int AS = BM + 8;
    constexpr int WS = C + 8;
    constexpr int NT = C / 8;
    constexpr int W4 = BK * C / 4 / 256;
    constexpr int NKB = D / BK;

    __shared__ unsigned As[BK * AS];
    __shared__ unsigned Ws[BK * WS];

    const int tid  = threadIdx.x;
    const int lane = tid & 31;
    const int warp = tid >> 5;
    const int row0 = blockIdx.x * BM;
    const int r0   = warp * 16 + (lane >> 2);
    const int kq   = lane & 3;
    const int nq   = lane >> 2;

    float acc[NT][4];
    #pragma unroll
    for (int i = 0; i < NT; i++)
        #pragma unroll
        for (int j = 0; j < 4; j++) acc[i][j] = 0.f;

    float4 aReg[4];
    #pragma unroll
    for (int j = 0; j < 4; j++) {
        int idx = tid + j * 256;
        int r = idx & 127, c4 = idx >> 7;
        aReg[j] = (row0 + r < N)
            ? __ldg((const float4*)(A + (size_t)(row0 + r) * D) + c4)
            : make_float4(0.f, 0.f, 0.f, 0.f);
    }

    for (int kb = 0; kb < NKB; kb++) {
        if (kb) __syncthreads();
        #pragma unroll
        for (int j = 0; j < 4; j++) {
            int idx = tid + j * 256;
            int r = idx & 127, c4 = idx >> 7;
            As[(c4 * 4 + 0) * AS + r] = to_tf32(aReg[j].x);
            As[(c4 * 4 + 1) * AS + r] = to_tf32(aReg[j].y);
            As[(c4 * 4 + 2) * AS + r] = to_tf32(aReg[j].z);
            As[(c4 * 4 + 3) * AS + r] = to_tf32(aReg[j].w);
        }
        #pragma unroll
        for (int j = 0; j < W4; j++) {
            int idx = (tid + j * 256) * 4;
            int k = idx / C, n = idx % C;
            float4 v = __ldg((const float4*)(W + (size_t)(kb * BK + k) * C + n));
            unsigned* w = &Ws[k * WS + n];
            w[0] = to_tf32(v.x);
            w[1] = to_tf32(v.y);
            w[2] = to_tf32(v.z);
            w[3] = to_tf32(v.w);
        }
        __syncthreads();

        if (kb + 1 < NKB) {     // prefetch next A chunk under the MMA work
            int kn = (kb + 1) * BK;
            #pragma unroll
            for (int j = 0; j < 4; j++) {
                int idx = tid + j * 256;
                int r = idx & 127, c4 = idx >> 7;
                aReg[j] = (row0 + r < N)
                    ? __ldg((const float4*)(A + (size_t)(row0 + r) * D + kn) + c4)
                    : make_float4(0.f, 0.f, 0.f, 0.f);
            }
        }

        #pragma unroll
        for (int ks = 0; ks < BK / 8; ks++) {
            int kk = ks * 8 + kq;
            unsigned a0 = As[kk * AS + r0];
            unsigned a1 = As[kk * AS + r0 + 8];
            unsigned a2 = As[(kk + 4) * AS + r0];
            unsigned a3 = As[(kk + 4) * AS + r0 + 8];
            #pragma unroll
            for (int nt = 0; nt < NT; nt++) {
                int n = nt * 8 + nq;
                unsigned b0 = Ws[kk * WS + n];
                unsigned b1 = Ws[(kk + 4) * WS + n];
                mma_tf32(acc[nt], a0, a1, a2, a3, b0, b1);
            }
        }
    }

    int rA = row0 + r0, rB = rA + 8;
    #pragma unroll
    for (int nt = 0; nt < NT; nt++) {
        int cc = nt * 8 + 2 * kq;
        if (rA < N)
            *(__half2*)(out + (size_t)rA * C + cc) = __floats2half2_rn(acc[nt][0], acc[nt][1]);
        if (rB < N)
            *(__half2*)(out + (size_t)rB * C + cc) = __floats2half2_rn(acc[nt][2], acc[nt][3]);
    }
}

// ---------- gather (128-wide, fp16 z): y[i] = relu(z[i] + sum_j z[j] + b) ---
// R8 shape: warp per node, hw parity (2 neighbors/wavefront), 4 loads in flight.
__global__ void gather128h_kernel(const __half* __restrict__ z,
                                  const float* __restrict__ bias,
                                  float* __restrict__ y, int N) {
    int node = (blockIdx.x * blockDim.x + threadIdx.x) >> 5;
    int lane = threadIdx.x & 31;
    if (node >= N) return;
    const uint4* z4 = (const uint4*)z;          // 16 per row
    const int off = g_off[node];
    const int deg = g_deg[node];
    const int* __restrict__ p = g_perm + off;
    const int hw = lane >> 4;                   // 0/1: neighbor parity
    const int cg = lane & 15;                   // col group (8 halves)

    ull a0 = 0, a1 = 0, a2 = 0, a3 = 0;
    if (hw == 0)
        hacc(a0, a1, a2, a3, __ldg(z4 + (size_t)node * 16 + cg));

    int t = 0;
    for (; t + 8 <= deg; t += 8) {
        int i = t + hw;
        int s0 = __ldg(p + i),     s1 = __ldg(p + i + 2);
        int s2 = __ldg(p + i + 4), s3 = __ldg(p + i + 6);
        uint4 v0 = __ldg(z4 + (size_t)s0 * 16 + cg);
        uint4 v1 = __ldg(z4 + (size_t)s1 * 16 + cg);
        uint4 v2 = __ldg(z4 + (size_t)s2 * 16 + cg);
        uint4 v3 = __ldg(z4 + (size_t)s3 * 16 + cg);
        hacc(a0, a1, a2, a3, v0);
        hacc(a0, a1, a2, a3, v1);
        hacc(a0, a1, a2, a3, v2);
        hacc(a0, a1, a2, a3, v3);
    }
    for (; t + 2 <= deg; t += 2) {
        int s = __ldg(p + t + hw);
        hacc(a0, a1, a2, a3, __ldg(z4 + (size_t)s * 16 + cg));
    }
    if (t < deg && hw == 0) {
        int s = __ldg(p + t);
        hacc(a0, a1, a2, a3, __ldg(z4 + (size_t)s * 16 + cg));
    }

    // fold half-warps (lane l += lane l+16; same cg)
    a0 = add2(a0, __shfl_down_sync(0xFFFFFFFFu, a0, 16));
    a1 = add2(a1, __shfl_down_sync(0xFFFFFFFFu, a1, 16));
    a2 = add2(a2, __shfl_down_sync(0xFFFFFFFFu, a2, 16));
    a3 = add2(a3, __shfl_down_sync(0xFFFFFFFFu, a3, 16));

    if (hw == 0) {
        float2 f0 = unpack2(a0), f1 = unpack2(a1);
        float2 f2 = unpack2(a2), f3 = unpack2(a3);
        float4 b0 = __ldg((const float4*)bias + cg * 2);
        float4 b1 = __ldg((const float4*)bias + cg * 2 + 1);
        float4 r0, r1;
        r0.x = fmaxf(f0.x + b0.x, 0.f); r0.y = fmaxf(f0.y + b0.y, 0.f);
        r0.z = fmaxf(f1.x + b0.z, 0.f); r0.w = fmaxf(f1.y + b0.w, 0.f);
        r1.x = fmaxf(f2.x + b1.x, 0.f); r1.y = fmaxf(f2.y + b1.y, 0.f);
        r1.z = fmaxf(f3.x + b1.z, 0.f); r1.w = fmaxf(f3.y + b1.w, 0.f);
        float* o = y + (size_t)node * 128 + cg * 8;
        *(float4*)o       = r0;
        *((float4*)o + 1) = r1;
    }
}

// ---------- gather (64-wide, fp16 z) + fused log_softmax -> d_out -----------
__global__ void gather64h_lsm_kernel(const __half* __restrict__ z,
                                     const float* __restrict__ bias,
                                     float* __restrict__ out, int N) {
    int node = (blockIdx.x * blockDim.x + threadIdx.x) >> 5;
    int lane = threadIdx.x & 31;
    if (node >= N) return;
    const uint4* z4 = (const uint4*)z;          // 8 per row
    const int off = g_off[node];
    const int deg = g_deg[node];
    const int* __restrict__ p = g_perm + off;
    const int q  = lane >> 3;                   // 0..3: neighbor sub-slot
    const int cg = lane & 7;                    // col group (8 halves)

    ull a0 = 0, a1 = 0, a2 = 0, a3 = 0;
    if (q == 0)
        hacc(a0, a1, a2, a3, __ldg(z4 + (size_t)node * 8 + cg));

    int t = 0;
    for (; t + 8 <= deg; t += 8) {
        int s0 = __ldg(p + t + q), s1 = __ldg(p + t + q + 4);
        uint4 v0 = __ldg(z4 + (size_t)s0 * 8 + cg);
        uint4 v1 = __ldg(z4 + (size_t)s1 * 8 + cg);
        hacc(a0, a1, a2, a3, v0);
        hacc(a0, a1, a2, a3, v1);
    }
    for (; t + 4 <= deg; t += 4) {
        int s = __ldg(p + t + q);
        hacc(a0, a1, a2, a3, __ldg(z4 + (size_t)s * 8 + cg));
    }
    int rem = deg - t;
    if (q < rem) {
        int s = __ldg(p + t + q);
        hacc(a0, a1, a2, a3, __ldg(z4 + (size_t)s * 8 + cg));
    }

    a0 = add2(a0, __shfl_down_sync(0xFFFFFFFFu, a0, 16));
    a1 = add2(a1, __shfl_down_sync(0xFFFFFFFFu, a1, 16));
    a2 = add2(a2, __shfl_down_sync(0xFFFFFFFFu, a2, 16));
    a3 = add2(a3, __shfl_down_sync(0xFFFFFFFFu, a3, 16));
    a0 = add2(a0, __shfl_down_sync(0xFFFFFFFFu, a0, 8));
    a1 = add2(a1, __shfl_down_sync(0xFFFFFFFFu, a1, 8));
    a2 = add2(a2, __shfl_down_sync(0xFFFFFFFFu, a2, 8));
    a3 = add2(a3, __shfl_down_sync(0xFFFFFFFFu, a3, 8));

    float2 f0 = unpack2(a0), f1 = unpack2(a1);
    float2 f2 = unpack2(a2), f3 = unpack2(a3);
    float4 b0 = __ldg((const float4*)bias + cg * 2);
    float4 b1 = __ldg((const float4*)bias + cg * 2 + 1);
    float v[8];
    v[0] = f0.x + b0.x; v[1] = f0.y + b0.y; v[2] = f1.x + b0.z; v[3] = f1.y + b0.w;
    v[4] = f2.x + b1.x; v[5] = f2.y + b1.y; v[6] = f3.x + b1.z; v[7] = f3.y + b1.w;

    float m = v[0];
    #pragma unroll
    for (int j = 1; j < 8; j++) m = fmaxf(m, v[j]);
    #pragma unroll
    for (int o = 4; o; o >>= 1) m = fmaxf(m, __shfl_xor_sync(0xFFFFFFFFu, m, o));
    float s = 0.f;
    #pragma unroll
    for (int j = 0; j < 8; j++) s += expf(v[j] - m);
    #pragma unroll
    for (int o = 4; o; o >>= 1) s += __shfl_xor_sync(0xFFFFFFFFu, s, o);
    float l = m + logf(s);

    if (q == 0) {
        float* o = out + (size_t)node * 64 + cg * 8;
        *(float4*)o       = make_float4(v[0] - l, v[1] - l, v[2] - l, v[3] - l);
        *((float4*)o + 1) = make_float4(v[4] - l, v[5] - l, v[6] - l, v[7] - l);
    }
}

// ---------------- launch ----------------
extern "C" void kernel_launch(void* const* d_in, const int* in_sizes, int n_in,
                              void* d_out, int out_size) {
    const float* feature = (const float*)d_in[0];
    const void*  ei      = d_in[1];
    const float* W1      = (const float*)d_in[2];
    const float* b1      = (const float*)d_in[3];
    const float* Wh      = (const float*)d_in[4];
    const float* bh      = (const float*)d_in[5];
    const float* Wo      = (const float*)d_in[6];
    const float* bo      = (const float*)d_in[7];
    float* out = (float*)d_out;

    const int N = N_NODES;
    int E = in_sizes[1] / 2;
    if (E > E_MAX) E = E_MAX;

    float*  y;  cudaGetSymbolAddress((void**)&y, g_y);
    __half* z;  cudaGetSymbolAddress((void**)&z, g_z);

    const int nB  = (N + 255) / 256;
    const int eB  = (E + 255) / 256;
    const int gaB = (N * 32 + 255) / 256;     // warp per node
    const int gmB = (N + 127) / 128;

    static cudaStream_t s2 = nullptr;
    static cudaEvent_t evF = nullptr, evJ = nullptr;
    if (s2 == nullptr) {
        cudaStreamCreateWithFlags(&s2, cudaStreamNonBlocking);
        cudaEventCreateWithFlags(&evF, cudaEventDisableTiming);
        cudaEventCreateWithFlags(&evJ, cudaEventDisableTiming);
    }

    // ---- fork: CSR build on side stream, concurrent with GEMM-1 ----
    cudaEventRecord(evF, 0);
    cudaStreamWaitEvent(s2, evF, 0);

    init_kernel<<<nB, 256, 0, s2>>>(ei);
    convert_kernel<<<eB, 256, 0, s2>>>(ei, E);
    scan_kernel<<<nB, 256, 0, s2>>>(N);
    fill_kernel<<<eB, 256, 0, s2>>>(E);
    cudaEventRecord(evJ, s2);

    gemm_tc_kernel<128><<<gmB, 256>>>(feature, W1, z, N);

    cudaStreamWaitEvent(0, evJ, 0);
    gather128h_kernel<<<gaB, 256>>>(z, b1, y, N);

    gemm_tc_kernel<128><<<gmB, 256>>>(y, Wh, z, N);
    gather128h_kernel<<<gaB, 256>>>(z, bh, y, N);

    gemm_tc_kernel<64><<<gmB, 256>>>(y, Wo, z, N);
    gather64h_lsm_kernel<<<gaB, 256>>>(z, bo, out, N);
}

// round 12
// speedup vs baseline: 1.4015x; 1.4015x over previous
#include <cuda_runtime.h>
#include <cuda_fp16.h>

#define N_NODES 50000
#define D 128
#define E_MAX 800000

typedef unsigned long long ull;

// ---------------- device scratch (no allocation allowed) ----------------
__device__ float  g_y[(size_t)N_NODES * D];   // gather outputs (fp32 activations)
__device__ __half g_z[(size_t)N_NODES * D];   // GEMM outputs (fp16, gathered)
__device__ int    g_is64;
__device__ int    g_src[E_MAX];
__device__ int    g_dst[E_MAX];
__device__ int    g_perm[E_MAX];              // CSR: src ids grouped by dst
__device__ int    g_deg[N_NODES];
__device__ int    g_off[N_NODES];
__device__ int    g_cur[N_NODES];
__device__ int    g_bsum[256];

// ---------------- f32x2 packed helpers ----------------
__device__ __forceinline__ ull pack2(float a, float b) {
    ull r;
    asm("mov.b64 %0, {%1, %2};" : "=l"(r) : "f"(a), "f"(b));
    return r;
}
__device__ __forceinline__ ull add2(ull a, ull b) {
    ull r;
    asm("add.rn.f32x2 %0, %1, %2;" : "=l"(r) : "l"(a), "l"(b));
    return r;
}
__device__ __forceinline__ float2 unpack2(ull v) {
    float2 r;
    asm("mov.b64 {%0, %1}, %2;" : "=f"(r.x), "=f"(r.y) : "l"(v));
    return r;
}

// accumulate 8 halves (uint4) into 4 packed f32x2 accumulators
__device__ __forceinline__ void hacc(ull& a0, ull& a1, ull& a2, ull& a3, uint4 v) {
    float2 f0 = __half22float2(*(const __half2*)&v.x);
    float2 f1 = __half22float2(*(const __half2*)&v.y);
    float2 f2 = __half22float2(*(const __half2*)&v.z);
    float2 f3 = __half22float2(*(const __half2*)&v.w);
    a0 = add2(a0, pack2(f0.x, f0.y));
    a1 = add2(a1, pack2(f1.x, f1.y));
    a2 = add2(a2, pack2(f2.x, f2.y));
    a3 = add2(a3, pack2(f3.x, f3.y));
}

// ---------------- tf32 mma helpers ----------------
__device__ __forceinline__ unsigned to_tf32(float f) {
    unsigned r;
    asm("cvt.rna.tf32.f32 %0, %1;" : "=r"(r) : "f"(f));
    return r;
}
__device__ __forceinline__ void mma_tf32(float* c, unsigned a0, unsigned a1,
                                         unsigned a2, unsigned a3,
                                         unsigned b0, unsigned b1) {
    asm volatile(
        "mma.sync.aligned.m16n8k8.row.col.f32.tf32.tf32.f32 "
        "{%0,%1,%2,%3}, {%4,%5,%6,%7}, {%8,%9}, {%0,%1,%2,%3};"
        : "+f"(c[0]), "+f"(c[1]), "+f"(c[2]), "+f"(c[3])
        : "r"(a0), "r"(a1), "r"(a2), "r"(a3), "r"(b0), "r"(b1));
}

// ---------------- init: zero degrees + dtype detect (fused) ----------------
__global__ void init_kernel(const void* __restrict__ ei) {
    int i = blockIdx.x * blockDim.x + threadIdx.x;
    if (i < N_NODES) g_deg[i] = 0;
    if (i == 0) {
        const long long* p = (const long long*)ei;
        int ok = 1;
        #pragma unroll
        for (int k = 0; k < 32; k++) {
            long long v = p[k];
            if (v < 0 || v >= N_NODES) ok = 0;
        }
        g_is64 = ok;
    }
}

// ---------------- CSR build: stage int32 + histogram ------------------------
__global__ void convert_kernel(const void* __restrict__ ei, int E) {
    int i = blockIdx.x * blockDim.x + threadIdx.x;
    if (i >= E) return;
    int s, d;
    if (g_is64) {
        const long long* p = (const long long*)ei;
        s = (int)__ldg(p + i);
        d = (int)__ldg(p + E + i);
    } else {
        const int* p = (const int*)ei;
        s = __ldg(p + i);
        d = __ldg(p + E + i);
    }
    g_src[i] = s;
    g_dst[i] = d;
    atomicAdd(&g_deg[d], 1);
}

// per-256-block exclusive scan of deg -> off(partial), totals to bsum
__global__ void scanA_kernel(int n) {
    __shared__ int sh[8];
    int t = threadIdx.x, i = blockIdx.x * 256 + t;
    int v = (i < n) ? g_deg[i] : 0;
    int lane = t & 31, w = t >> 5;
    int x = v;
    #pragma unroll
    for (int o = 1; o < 32; o <<= 1) {
        int y = __shfl_up_sync(0xFFFFFFFFu, x, o);
        if (lane >= o) x += y;
    }
    if (lane == 31) sh[w] = x;
    __syncthreads();
    if (t < 8) {
        int s = sh[t];
        #pragma unroll
        for (int o = 1; o < 8; o <<= 1) {
            int y = __shfl_up_sync(0xFFu, s, o);
            if (t >= o) s += y;
        }
        sh[t] = s;
    }
    __syncthreads();
    int incl = x + (w ? sh[w - 1] : 0);
    if (i < n) g_off[i] = incl - v;
    if (t == 255) g_bsum[blockIdx.x] = incl;
}

// add prefix of block sums (each block reduces bsum[0..b) itself)
__global__ void scanC_kernel(int n) {
    __shared__ int wsum[8];
    int b = blockIdx.x, t = threadIdx.x;
    int s = 0;
    for (int j = t; j < b; j += 256) s += g_bsum[j];
    #pragma unroll
    for (int o = 16; o; o >>= 1) s += __shfl_xor_sync(0xFFFFFFFFu, s, o);
    if ((t & 31) == 0) wsum[t >> 5] = s;
    __syncthreads();
    int base = 0;
    #pragma unroll
    for (int w = 0; w < 8; w++) base += wsum[w];
    int i = b * 256 + t;
    if (i < n) {
        int o = g_off[i] + base;
        g_off[i] = o;
        g_cur[i] = o;
    }
}

__global__ void fill_kernel(int E) {
    int i = blockIdx.x * blockDim.x + threadIdx.x;
    if (i >= E) return;
    int d = g_dst[i];
    int p = atomicAdd(&g_cur[d], 1);
    g_perm[p] = g_src[i];
}

// ---------------- tf32 tensor-core GEMM: z = A @ W (fp16 out) ---------------
// A-chunk register-prefetched; W staged per-chunk (L2-hot).
template <int C>
__global__ __launch_bounds__(256, 2)
void gemm_tc_kernel(const float* __restrict__ A,
                    const float* __restrict__ W,
                    __half* __restrict__ out,
                    int N) {
    constexpr int BM = 128;
    constexpr int BK = 32;
    constexpr int AS = BM + 8;
    constexpr int WS = C + 8;
    constexpr int NT = C / 8;
    constexpr int W4 = BK * C / 4 / 256;
    constexpr int NKB = D / BK;

    __shared__ unsigned As[BK * AS];
    __shared__ unsigned Ws[BK * WS];

    const int tid  = threadIdx.x;
    const int lane = tid & 31;
    const int warp = tid >> 5;
    const int row0 = blockIdx.x * BM;
    const int r0   = warp * 16 + (lane >> 2);
    const int kq   = lane & 3;
    const int nq   = lane >> 2;

    float acc[NT][4];
    #pragma unroll
    for (int i = 0; i < NT; i++)
        #pragma unroll
        for (int j = 0; j < 4; j++) acc[i][j] = 0.f;

    float4 aReg[4];
    #pragma unroll
    for (int j = 0; j < 4; j++) {
        int idx = tid + j * 256;
        int r = idx & 127, c4 = idx >> 7;
        aReg[j] = (row0 + r < N)
            ? __ldg((const float4*)(A + (size_t)(row0 + r) * D) + c4)
            : make_float4(0.f, 0.f, 0.f, 0.f);
    }

    for (int kb = 0; kb < NKB; kb++) {
        if (kb) __syncthreads();
        #pragma unroll
        for (int j = 0; j < 4; j++) {
            int idx = tid + j * 256;
            int r = idx & 127, c4 = idx >> 7;
            As[(c4 * 4 + 0) * AS + r] = to_tf32(aReg[j].x);
            As[(c4 * 4 + 1) * AS + r] = to_tf32(aReg[j].y);
            As[(c4 * 4 + 2) * AS + r] = to_tf32(aReg[j].z);
            As[(c4 * 4 + 3) * AS + r] = to_tf32(aReg[j].w);
        }
        #pragma unroll
        for (int j = 0; j < W4; j++) {
            int idx = (tid + j * 256) * 4;
            int k = idx / C, n = idx % C;
            float4 v = __ldg((const float4*)(W + (size_t)(kb * BK + k) * C + n));
            unsigned* w = &Ws[k * WS + n];
            w[0] = to_tf32(v.x);
            w[1] = to_tf32(v.y);
            w[2] = to_tf32(v.z);
            w[3] = to_tf32(v.w);
        }
        __syncthreads();

        if (kb + 1 < NKB) {     // prefetch next A chunk under the MMA work
            int kn = (kb + 1) * BK;
            #pragma unroll
            for (int j = 0; j < 4; j++) {
                int idx = tid + j * 256;
                int r = idx & 127, c4 = idx >> 7;
                aReg[j] = (row0 + r < N)
                    ? __ldg((const float4*)(A + (size_t)(row0 + r) * D + kn) + c4)
                    : make_float4(0.f, 0.f, 0.f, 0.f);
            }
        }

        #pragma unroll
        for (int ks = 0; ks < BK / 8; ks++) {
            int kk = ks * 8 + kq;
            unsigned a0 = As[kk * AS + r0];
            unsigned a1 = As[kk * AS + r0 + 8];
            unsigned a2 = As[(kk + 4) * AS + r0];
            unsigned a3 = As[(kk + 4) * AS + r0 + 8];
            #pragma unroll
            for (int nt = 0; nt < NT; nt++) {
                int n = nt * 8 + nq;
                unsigned b0 = Ws[kk * WS + n];
                unsigned b1 = Ws[(kk + 4) * WS + n];
                mma_tf32(acc[nt], a0, a1, a2, a3, b0, b1);
            }
        }
    }

    int rA = row0 + r0, rB = rA + 8;
    #pragma unroll
    for (int nt = 0; nt < NT; nt++) {
        int cc = nt * 8 + 2 * kq;
        if (rA < N)
            *(__half2*)(out + (size_t)rA * C + cc) = __floats2half2_rn(acc[nt][0], acc[nt][1]);
        if (rB < N)
            *(__half2*)(out + (size_t)rB * C + cc) = __floats2half2_rn(acc[nt][2], acc[nt][3]);
    }
}

// ---------- gather (128-wide, fp16 z): y[i] = relu(z[i] + sum_j z[j] + b) ---
// R8 shape: warp per node, hw parity (2 neighbors/wavefront), 4 loads in flight.
__global__ void gather128h_kernel(const __half* __restrict__ z,
                                  const float* __restrict__ bias,
                                  float* __restrict__ y, int N) {
    int node = (blockIdx.x * blockDim.x + threadIdx.x) >> 5;
    int lane = threadIdx.x & 31;
    if (node >= N) return;
    const uint4* z4 = (const uint4*)z;          // 16 per row
    const int off = g_off[node];
    const int deg = g_deg[node];
    const int* __restrict__ p = g_perm + off;
    const int hw = lane >> 4;                   // 0/1: neighbor parity
    const int cg = lane & 15;                   // col group (8 halves)

    ull a0 = 0, a1 = 0, a2 = 0, a3 = 0;
    if (hw == 0)
        hacc(a0, a1, a2, a3, __ldg(z4 + (size_t)node * 16 + cg));

    int t = 0;
    for (; t + 8 <= deg; t += 8) {
        int i = t + hw;
        int s0 = __ldg(p + i),     s1 = __ldg(p + i + 2);
        int s2 = __ldg(p + i + 4), s3 = __ldg(p + i + 6);
        uint4 v0 = __ldg(z4 + (size_t)s0 * 16 + cg);
        uint4 v1 = __ldg(z4 + (size_t)s1 * 16 + cg);
        uint4 v2 = __ldg(z4 + (size_t)s2 * 16 + cg);
        uint4 v3 = __ldg(z4 + (size_t)s3 * 16 + cg);
        hacc(a0, a1, a2, a3, v0);
        hacc(a0, a1, a2, a3, v1);
        hacc(a0, a1, a2, a3, v2);
        hacc(a0, a1, a2, a3, v3);
    }
    for (; t + 2 <= deg; t += 2) {
        int s = __ldg(p + t + hw);
        hacc(a0, a1, a2, a3, __ldg(z4 + (size_t)s * 16 + cg));
    }
    if (t < deg && hw == 0) {
        int s = __ldg(p + t);
        hacc(a0, a1, a2, a3, __ldg(z4 + (size_t)s * 16 + cg));
    }

    // fold half-warps (lane l += lane l+16; same cg)
    a0 = add2(a0, __shfl_down_sync(0xFFFFFFFFu, a0, 16));
    a1 = add2(a1, __shfl_down_sync(0xFFFFFFFFu, a1, 16));
    a2 = add2(a2, __shfl_down_sync(0xFFFFFFFFu, a2, 16));
    a3 = add2(a3, __shfl_down_sync(0xFFFFFFFFu, a3, 16));

    if (hw == 0) {
        float2 f0 = unpack2(a0), f1 = unpack2(a1);
        float2 f2 = unpack2(a2), f3 = unpack2(a3);
        float4 b0 = __ldg((const float4*)bias + cg * 2);
        float4 b1 = __ldg((const float4*)bias + cg * 2 + 1);
        float4 r0, r1;
        r0.x = fmaxf(f0.x + b0.x, 0.f); r0.y = fmaxf(f0.y + b0.y, 0.f);
        r0.z = fmaxf(f1.x + b0.z, 0.f); r0.w = fmaxf(f1.y + b0.w, 0.f);
        r1.x = fmaxf(f2.x + b1.x, 0.f); r1.y = fmaxf(f2.y + b1.y, 0.f);
        r1.z = fmaxf(f3.x + b1.z, 0.f); r1.w = fmaxf(f3.y + b1.w, 0.f);
        float* o = y + (size_t)node * 128 + cg * 8;
        *(float4*)o       = r0;
        *((float4*)o + 1) = r1;
    }
}

// ---------- gather (64-wide, fp16 z) + fused log_softmax -> d_out -----------
__global__ void gather64h_lsm_kernel(const __half* __restrict__ z,
                                     const float* __restrict__ bias,
                                     float* __restrict__ out, int N) {
    int node = (blockIdx.x * blockDim.x + threadIdx.x) >> 5;
    int lane = threadIdx.x & 31;
    if (node >= N) return;
    const uint4* z4 = (const uint4*)z;          // 8 per row
    const int off = g_off[node];
    const int deg = g_deg[node];
    const int* __restrict__ p = g_perm + off;
    const int q  = lane >> 3;                   // 0..3: neighbor sub-slot
    const int cg = lane & 7;                    // col group (8 halves)

    ull a0 = 0, a1 = 0, a2 = 0, a3 = 0;
    if (q == 0)
        hacc(a0, a1, a2, a3, __ldg(z4 + (size_t)node * 8 + cg));

    int t = 0;
    for (; t + 8 <= deg; t += 8) {
        int s0 = __ldg(p + t + q), s1 = __ldg(p + t + q + 4);
        uint4 v0 = __ldg(z4 + (size_t)s0 * 8 + cg);
        uint4 v1 = __ldg(z4 + (size_t)s1 * 8 + cg);
        hacc(a0, a1, a2, a3, v0);
        hacc(a0, a1, a2, a3, v1);
    }
    for (; t + 4 <= deg; t += 4) {
        int s = __ldg(p + t + q);
        hacc(a0, a1, a2, a3, __ldg(z4 + (size_t)s * 8 + cg));
    }
    int rem = deg - t;
    if (q < rem) {
        int s = __ldg(p + t + q);
        hacc(a0, a1, a2, a3, __ldg(z4 + (size_t)s * 8 + cg));
    }

    a0 = add2(a0, __shfl_down_sync(0xFFFFFFFFu, a0, 16));
    a1 = add2(a1, __shfl_down_sync(0xFFFFFFFFu, a1, 16));
    a2 = add2(a2, __shfl_down_sync(0xFFFFFFFFu, a2, 16));
    a3 = add2(a3, __shfl_down_sync(0xFFFFFFFFu, a3, 16));
    a0 = add2(a0, __shfl_down_sync(0xFFFFFFFFu, a0, 8));
    a1 = add2(a1, __shfl_down_sync(0xFFFFFFFFu, a1, 8));
    a2 = add2(a2, __shfl_down_sync(0xFFFFFFFFu, a2, 8));
    a3 = add2(a3, __shfl_down_sync(0xFFFFFFFFu, a3, 8));

    float2 f0 = unpack2(a0), f1 = unpack2(a1);
    float2 f2 = unpack2(a2), f3 = unpack2(a3);
    float4 b0 = __ldg((const float4*)bias + cg * 2);
    float4 b1 = __ldg((const float4*)bias + cg * 2 + 1);
    float v[8];
    v[0] = f0.x + b0.x; v[1] = f0.y + b0.y; v[2] = f1.x + b0.z; v[3] = f1.y + b0.w;
    v[4] = f2.x + b1.x; v[5] = f2.y + b1.y; v[6] = f3.x + b1.z; v[7] = f3.y + b1.w;

    float m = v[0];
    #pragma unroll
    for (int j = 1; j < 8; j++) m = fmaxf(m, v[j]);
    #pragma unroll
    for (int o = 4; o; o >>= 1) m = fmaxf(m, __shfl_xor_sync(0xFFFFFFFFu, m, o));
    float s = 0.f;
    #pragma unroll
    for (int j = 0; j < 8; j++) s += expf(v[j] - m);
    #pragma unroll
    for (int o = 4; o; o >>= 1) s += __shfl_xor_sync(0xFFFFFFFFu, s, o);
    float l = m + logf(s);

    if (q == 0) {
        float* o = out + (size_t)node * 64 + cg * 8;
        *(float4*)o       = make_float4(v[0] - l, v[1] - l, v[2] - l, v[3] - l);
        *((float4*)o + 1) = make_float4(v[4] - l, v[5] - l, v[6] - l, v[7] - l);
    }
}

// ---------------- launch ----------------
extern "C" void kernel_launch(void* const* d_in, const int* in_sizes, int n_in,
                              void* d_out, int out_size) {
    const float* feature = (const float*)d_in[0];
    const void*  ei      = d_in[1];
    const float* W1      = (const float*)d_in[2];
    const float* b1      = (const float*)d_in[3];
    const float* Wh      = (const float*)d_in[4];
    const float* bh      = (const float*)d_in[5];
    const float* Wo      = (const float*)d_in[6];
    const float* bo      = (const float*)d_in[7];
    float* out = (float*)d_out;

    const int N = N_NODES;
    int E = in_sizes[1] / 2;
    if (E > E_MAX) E = E_MAX;

    float*  y;  cudaGetSymbolAddress((void**)&y, g_y);
    __half* z;  cudaGetSymbolAddress((void**)&z, g_z);

    const int nB  = (N + 255) / 256;
    const int eB  = (E + 255) / 256;
    const int gaB = (N * 32 + 255) / 256;     // warp per node
    const int gmB = (N + 127) / 128;

    static cudaStream_t s2 = nullptr;
    static cudaEvent_t evF = nullptr, evJ = nullptr;
    if (s2 == nullptr) {
        cudaStreamCreateWithFlags(&s2, cudaStreamNonBlocking);
        cudaEventCreateWithFlags(&evF, cudaEventDisableTiming);
        cudaEventCreateWithFlags(&evJ, cudaEventDisableTiming);
    }

    // ---- fork: CSR build on side stream, concurrent with GEMM-1 ----
    cudaEventRecord(evF, 0);
    cudaStreamWaitEvent(s2, evF, 0);

    init_kernel<<<nB, 256, 0, s2>>>(ei);
    convert_kernel<<<eB, 256, 0, s2>>>(ei, E);
    scanA_kernel<<<nB, 256, 0, s2>>>(N);
    scanC_kernel<<<nB, 256, 0, s2>>>(N);
    fill_kernel<<<eB, 256, 0, s2>>>(E);
    cudaEventRecord(evJ, s2);

    gemm_tc_kernel<128><<<gmB, 256>>>(feature, W1, z, N);

    cudaStreamWaitEvent(0, evJ, 0);
    gather128h_kernel<<<gaB, 256>>>(z, b1, y, N);

    gemm_tc_kernel<128><<<gmB, 256>>>(y, Wh, z, N);
    gather128h_kernel<<<gaB, 256>>>(z, bh, y, N);

    gemm_tc_kernel<64><<<gmB, 256>>>(y, Wo, z, N);
    gather64h_lsm_kernel<<<gaB, 256>>>(z, bo, out, N);
}

// round 15
// speedup vs baseline: 1.4174x; 1.0114x over previous
#include <cuda_runtime.h>
#include <cuda_fp16.h>

#define N_NODES 50000
#define D 128
#define E_MAX 800000

typedef unsigned long long ull;

// ---------------- device scratch (no allocation allowed) ----------------
__device__ float  g_y[(size_t)N_NODES * D];   // gather outputs (fp32 activations)
__device__ __half g_z[(size_t)N_NODES * D];   // GEMM outputs (fp16, gathered)
__device__ int    g_is64;
__device__ int    g_src[E_MAX];
__device__ int    g_dst[E_MAX];
__device__ int    g_perm[E_MAX];              // CSR: src ids grouped by dst
__device__ int    g_deg[N_NODES];
__device__ int    g_off[N_NODES];
__device__ int    g_cur[N_NODES];
__device__ int    g_bsum[256];

// ---------------- f32x2 packed helpers ----------------
__device__ __forceinline__ ull pack2(float a, float b) {
    ull r;
    asm("mov.b64 %0, {%1, %2};" : "=l"(r) : "f"(a), "f"(b));
    return r;
}
__device__ __forceinline__ ull add2(ull a, ull b) {
    ull r;
    asm("add.rn.f32x2 %0, %1, %2;" : "=l"(r) : "l"(a), "l"(b));
    return r;
}
__device__ __forceinline__ float2 unpack2(ull v) {
    float2 r;
    asm("mov.b64 {%0, %1}, %2;" : "=f"(r.x), "=f"(r.y) : "l"(v));
    return r;
}

// accumulate 8 halves (uint4) into 4 packed f32x2 accumulators
__device__ __forceinline__ void hacc(ull& a0, ull& a1, ull& a2, ull& a3, uint4 v) {
    float2 f0 = __half22float2(*(const __half2*)&v.x);
    float2 f1 = __half22float2(*(const __half2*)&v.y);
    float2 f2 = __half22float2(*(const __half2*)&v.z);
    float2 f3 = __half22float2(*(const __half2*)&v.w);
    a0 = add2(a0, pack2(f0.x, f0.y));
    a1 = add2(a1, pack2(f1.x, f1.y));
    a2 = add2(a2, pack2(f2.x, f2.y));
    a3 = add2(a3, pack2(f3.x, f3.y));
}

// ---------------- tf32 mma helpers ----------------
__device__ __forceinline__ unsigned to_tf32(float f) {
    unsigned r;
    asm("cvt.rna.tf32.f32 %0, %1;" : "=r"(r) : "f"(f));
    return r;
}
__device__ __forceinline__ void mma_tf32(float* c, unsigned a0, unsigned a1,
                                         unsigned a2, unsigned a3,
                                         unsigned b0, unsigned b1) {
    asm volatile(
        "mma.sync.aligned.m16n8k8.row.col.f32.tf32.tf32.f32 "
        "{%0,%1,%2,%3}, {%4,%5,%6,%7}, {%8,%9}, {%0,%1,%2,%3};"
        : "+f"(c[0]), "+f"(c[1]), "+f"(c[2]), "+f"(c[3])
        : "r"(a0), "r"(a1), "r"(a2), "r"(a3), "r"(b0), "r"(b1));
}

// ---------------- init: zero degrees + dtype detect (fused) ----------------
__global__ void init_kernel(const void* __restrict__ ei) {
    int i = blockIdx.x * blockDim.x + threadIdx.x;
    if (i < N_NODES) g_deg[i] = 0;
    if (i == 0) {
        const long long* p = (const long long*)ei;
        int ok = 1;
        #pragma unroll
        for (int k = 0; k < 32; k++) {
            long long v = p[k];
            if (v < 0 || v >= N_NODES) ok = 0;
        }
        g_is64 = ok;
    }
}

// ---------------- CSR build: stage int32 + histogram ------------------------
__global__ void convert_kernel(const void* __restrict__ ei, int E) {
    int i = blockIdx.x * blockDim.x + threadIdx.x;
    if (i >= E) return;
    int s, d;
    if (g_is64) {
        const long long* p = (const long long*)ei;
        s = (int)__ldg(p + i);
        d = (int)__ldg(p + E + i);
    } else {
        const int* p = (const int*)ei;
        s = __ldg(p + i);
        d = __ldg(p + E + i);
    }
    g_src[i] = s;
    g_dst[i] = d;
    atomicAdd(&g_deg[d], 1);
}

// per-256-block exclusive scan of deg -> off(partial), totals to bsum
__global__ void scanA_kernel(int n) {
    __shared__ int sh[8];
    int t = threadIdx.x, i = blockIdx.x * 256 + t;
    int v = (i < n) ? g_deg[i] : 0;
    int lane = t & 31, w = t >> 5;
    int x = v;
    #pragma unroll
    for (int o = 1; o < 32; o <<= 1) {
        int y = __shfl_up_sync(0xFFFFFFFFu, x, o);
        if (lane >= o) x += y;
    }
    if (lane == 31) sh[w] = x;
    __syncthreads();
    if (t < 8) {
        int s = sh[t];
        #pragma unroll
        for (int o = 1; o < 8; o <<= 1) {
            int y = __shfl_up_sync(0xFFu, s, o);
            if (t >= o) s += y;
        }
        sh[t] = s;
    }
    __syncthreads();
    int incl = x + (w ? sh[w - 1] : 0);
    if (i < n) g_off[i] = incl - v;
    if (t == 255) g_bsum[blockIdx.x] = incl;
}

// add prefix of block sums (each block reduces bsum[0..b) itself)
__global__ void scanC_kernel(int n) {
    __shared__ int wsum[8];
    int b = blockIdx.x, t = threadIdx.x;
    int s = 0;
    for (int j = t; j < b; j += 256) s += g_bsum[j];
    #pragma unroll
    for (int o = 16; o; o >>= 1) s += __shfl_xor_sync(0xFFFFFFFFu, s, o);
    if ((t & 31) == 0) wsum[t >> 5] = s;
    __syncthreads();
    int base = 0;
    #pragma unroll
    for (int w = 0; w < 8; w++) base += wsum[w];
    int i = b * 256 + t;
    if (i < n) {
        int o = g_off[i] + base;
        g_off[i] = o;
        g_cur[i] = o;
    }
}

__global__ void fill_kernel(int E) {
    int i = blockIdx.x * blockDim.x + threadIdx.x;
    if (i >= E) return;
    int d = g_dst[i];
    int p = atomicAdd(&g_cur[d], 1);
    g_perm[p] = g_src[i];
}

// ---------------- tf32 tensor-core GEMM: z = A @ W (fp16 out) ---------------
// R8 form: stage A+W from global each chunk; no register prefetch.
template <int C>
__global__ __launch_bounds__(256, 2)
void gemm_tc_kernel(const float* __restrict__ A,
                    const float* __restrict__ W,
                    __half* __restrict__ out,
                    int N) {
    constexpr int BM = 128;
    constexpr int BK = 32;
    constexpr int AS = BM + 8;
    constexpr int WS = C + 8;
    constexpr int NT = C / 8;
    constexpr int W4 = BK * C / 4 / 256;

    __shared__ unsigned As[BK * AS];
    __shared__ unsigned Ws[BK * WS];

    const int tid  = threadIdx.x;
    const int lane = tid & 31;
    const int warp = tid >> 5;
    const int row0 = blockIdx.x * BM;
    const int r0   = warp * 16 + (lane >> 2);
    const int kq   = lane & 3;
    const int nq   = lane >> 2;

    float acc[NT][4];
    #pragma unroll
    for (int i = 0; i < NT; i++)
        #pragma unroll
        for (int j = 0; j < 4; j++) acc[i][j] = 0.f;

    for (int kb0 = 0; kb0 < D; kb0 += BK) {
        if (kb0) __syncthreads();
        #pragma unroll
        for (int j = 0; j < 4; j++) {
            int idx = tid + j * 256;
            int r = idx & 127, c4 = idx >> 7;
            float4 v = make_float4(0.f, 0.f, 0.f, 0.f);
            if (row0 + r < N)
                v = __ldg((const float4*)(A + (size_t)(row0 + r) * D + kb0) + c4);
            As[(c4 * 4 + 0) * AS + r] = to_tf32(v.x);
            As[(c4 * 4 + 1) * AS + r] = to_tf32(v.y);
            As[(c4 * 4 + 2) * AS + r] = to_tf32(v.z);
            As[(c4 * 4 + 3) * AS + r] = to_tf32(v.w);
        }
        #pragma unroll
        for (int j = 0; j < W4; j++) {
            int idx = (tid + j * 256) * 4;
            int k = idx / C, n = idx % C;
            float4 v = __ldg((const float4*)(W + (size_t)(kb0 + k) * C + n));
            unsigned* w = &Ws[k * WS + n];
            w[0] = to_tf32(v.x);
            w[1] = to_tf32(v.y);
            w[2] = to_tf32(v.z);
            w[3] = to_tf32(v.w);
        }
        __syncthreads();

        #pragma unroll
        for (int ks = 0; ks < BK / 8; ks++) {
            int kk = ks * 8 + kq;
            unsigned a0 = As[kk * AS + r0];
            unsigned a1 = As[kk * AS + r0 + 8];
            unsigned a2 = As[(kk + 4) * AS + r0];
            unsigned a3 = As[(kk + 4) * AS + r0 + 8];
            #pragma unroll
            for (int nt = 0; nt < NT; nt++) {
                int n = nt * 8 + nq;
                unsigned b0 = Ws[kk * WS + n];
                unsigned b1 = Ws[(kk + 4) * WS + n];
                mma_tf32(acc[nt], a0, a1, a2, a3, b0, b1);
            }
        }
    }

    int rA = row0 + r0, rB = rA + 8;
    #pragma unroll
    for (int nt = 0; nt < NT; nt++) {
        int cc = nt * 8 + 2 * kq;
        if (rA < N)
            *(__half2*)(out + (size_t)rA * C + cc) = __floats2half2_rn(acc[nt][0], acc[nt][1]);
        if (rB < N)
            *(__half2*)(out + (size_t)rB * C + cc) = __floats2half2_rn(acc[nt][2], acc[nt][3]);
    }
}

// ---------- gather (128-wide, fp16 z): y[i] = relu(z[i] + sum_j z[j] + b) ---
// Warp per node, hw parity (2 neighbors/wavefront), 4 loads in flight.
__global__ void gather128h_kernel(const __half* __restrict__ z,
                                  const float* __restrict__ bias,
                                  float* __restrict__ y, int N) {
    int node = (blockIdx.x * blockDim.x + threadIdx.x) >> 5;
    int lane = threadIdx.x & 31;
    if (node >= N) return;
    const uint4* z4 = (const uint4*)z;          // 16 per row
    const int off = g_off[node];
    const int deg = g_deg[node];
    const int* __restrict__ p = g_perm + off;
    const int hw = lane >> 4;                   // 0/1: neighbor parity
    const int cg = lane & 15;                   // col group (8 halves)

    ull a0 = 0, a1 = 0, a2 = 0, a3 = 0;
    if (hw == 0)
        hacc(a0, a1, a2, a3, __ldg(z4 + (size_t)node * 16 + cg));

    int t = 0;
    for (; t + 8 <= deg; t += 8) {
        int i = t + hw;
        int s0 = __ldg(p + i),     s1 = __ldg(p + i + 2);
        int s2 = __ldg(p + i + 4), s3 = __ldg(p + i + 6);
        uint4 v0 = __ldg(z4 + (size_t)s0 * 16 + cg);
        uint4 v1 = __ldg(z4 + (size_t)s1 * 16 + cg);
        uint4 v2 = __ldg(z4 + (size_t)s2 * 16 + cg);
        uint4 v3 = __ldg(z4 + (size_t)s3 * 16 + cg);
        hacc(a0, a1, a2, a3, v0);
        hacc(a0, a1, a2, a3, v1);
        hacc(a0, a1, a2, a3, v2);
        hacc(a0, a1, a2, a3, v3);
    }
    for (; t + 2 <= deg; t += 2) {
        int s = __ldg(p + t + hw);
        hacc(a0, a1, a2, a3, __ldg(z4 + (size_t)s * 16 + cg));
    }
    if (t < deg && hw == 0) {
        int s = __ldg(p + t);
        hacc(a0, a1, a2, a3, __ldg(z4 + (size_t)s * 16 + cg));
    }

    // fold half-warps (lane l += lane l+16; same cg)
    a0 = add2(a0, __shfl_down_sync(0xFFFFFFFFu, a0, 16));
    a1 = add2(a1, __shfl_down_sync(0xFFFFFFFFu, a1, 16));
    a2 = add2(a2, __shfl_down_sync(0xFFFFFFFFu, a2, 16));
    a3 = add2(a3, __shfl_down_sync(0xFFFFFFFFu, a3, 16));

    if (hw == 0) {
        float2 f0 = unpack2(a0), f1 = unpack2(a1);
        float2 f2 = unpack2(a2), f3 = unpack2(a3);
        float4 b0 = __ldg((const float4*)bias + cg * 2);
        float4 b1 = __ldg((const float4*)bias + cg * 2 + 1);
        float4 r0, r1;
        r0.x = fmaxf(f0.x + b0.x, 0.f); r0.y = fmaxf(f0.y + b0.y, 0.f);
        r0.z = fmaxf(f1.x + b0.z, 0.f); r0.w = fmaxf(f1.y + b0.w, 0.f);
        r1.x = fmaxf(f2.x + b1.x, 0.f); r1.y = fmaxf(f2.y + b1.y, 0.f);
        r1.z = fmaxf(f3.x + b1.z, 0.f); r1.w = fmaxf(f3.y + b1.w, 0.f);
        float* o = y + (size_t)node * 128 + cg * 8;
        *(float4*)o       = r0;
        *((float4*)o + 1) = r1;
    }
}

// ---------- gather (64-wide, fp16 z) + fused log_softmax -> d_out -----------
__global__ void gather64h_lsm_kernel(const __half* __restrict__ z,
                                     const float* __restrict__ bias,
                                     float* __restrict__ out, int N) {
    int node = (blockIdx.x * blockDim.x + threadIdx.x) >> 5;
    int lane = threadIdx.x & 31;
    if (node >= N) return;
    const uint4* z4 = (const uint4*)z;          // 8 per row
    const int off = g_off[node];
    const int deg = g_deg[node];
    const int* __restrict__ p = g_perm + off;
    const int q  = lane >> 3;                   // 0..3: neighbor sub-slot
    const int cg = lane & 7;                    // col group (8 halves)

    ull a0 = 0, a1 = 0, a2 = 0, a3 = 0;
    if (q == 0)
        hacc(a0, a1, a2, a3, __ldg(z4 + (size_t)node * 8 + cg));

    int t = 0;
    for (; t + 8 <= deg; t += 8) {
        int s0 = __ldg(p + t + q), s1 = __ldg(p + t + q + 4);
        uint4 v0 = __ldg(z4 + (size_t)s0 * 8 + cg);
        uint4 v1 = __ldg(z4 + (size_t)s1 * 8 + cg);
        hacc(a0, a1, a2, a3, v0);
        hacc(a0, a1, a2, a3, v1);
    }
    for (; t + 4 <= deg; t += 4) {
        int s = __ldg(p + t + q);
        hacc(a0, a1, a2, a3, __ldg(z4 + (size_t)s * 8 + cg));
    }
    int rem = deg - t;
    if (q < rem) {
        int s = __ldg(p + t + q);
        hacc(a0, a1, a2, a3, __ldg(z4 + (size_t)s * 8 + cg));
    }

    a0 = add2(a0, __shfl_down_sync(0xFFFFFFFFu, a0, 16));
    a1 = add2(a1, __shfl_down_sync(0xFFFFFFFFu, a1, 16));
    a2 = add2(a2, __shfl_down_sync(0xFFFFFFFFu, a2, 16));
    a3 = add2(a3, __shfl_down_sync(0xFFFFFFFFu, a3, 16));
    a0 = add2(a0, __shfl_down_sync(0xFFFFFFFFu, a0, 8));
    a1 = add2(a1, __shfl_down_sync(0xFFFFFFFFu, a1, 8));
    a2 = add2(a2, __shfl_down_sync(0xFFFFFFFFu, a2, 8));
    a3 = add2(a3, __shfl_down_sync(0xFFFFFFFFu, a3, 8));

    float2 f0 = unpack2(a0), f1 = unpack2(a1);
    float2 f2 = unpack2(a2), f3 = unpack2(a3);
    float4 b0 = __ldg((const float4*)bias + cg * 2);
    float4 b1 = __ldg((const float4*)bias + cg * 2 + 1);
    float v[8];
    v[0] = f0.x + b0.x; v[1] = f0.y + b0.y; v[2] = f1.x + b0.z; v[3] = f1.y + b0.w;
    v[4] = f2.x + b1.x; v[5] = f2.y + b1.y; v[6] = f3.x + b1.z; v[7] = f3.y + b1.w;

    float m = v[0];
    #pragma unroll
    for (int j = 1; j < 8; j++) m = fmaxf(m, v[j]);
    #pragma unroll
    for (int o = 4; o; o >>= 1) m = fmaxf(m, __shfl_xor_sync(0xFFFFFFFFu, m, o));
    float s = 0.f;
    #pragma unroll
    for (int j = 0; j < 8; j++) s += expf(v[j] - m);
    #pragma unroll
    for (int o = 4; o; o >>= 1) s += __shfl_xor_sync(0xFFFFFFFFu, s, o);
    float l = m + logf(s);

    if (q == 0) {
        float* o = out + (size_t)node * 64 + cg * 8;
        *(float4*)o       = make_float4(v[0] - l, v[1] - l, v[2] - l, v[3] - l);
        *((float4*)o + 1) = make_float4(v[4] - l, v[5] - l, v[6] - l, v[7] - l);
    }
}

// ---------------- launch ----------------
extern "C" void kernel_launch(void* const* d_in, const int* in_sizes, int n_in,
                              void* d_out, int out_size) {
    const float* feature = (const float*)d_in[0];
    const void*  ei      = d_in[1];
    const float* W1      = (const float*)d_in[2];
    const float* b1      = (const float*)d_in[3];
    const float* Wh      = (const float*)d_in[4];
    const float* bh      = (const float*)d_in[5];
    const float* Wo      = (const float*)d_in[6];
    const float* bo      = (const float*)d_in[7];
    float* out = (float*)d_out;

    const int N = N_NODES;
    int E = in_sizes[1] / 2;
    if (E > E_MAX) E = E_MAX;

    float*  y;  cudaGetSymbolAddress((void**)&y, g_y);
    __half* z;  cudaGetSymbolAddress((void**)&z, g_z);

    const int nB  = (N + 255) / 256;
    const int eB  = (E + 255) / 256;
    const int gaB = (N * 32 + 255) / 256;     // warp per node
    const int gmB = (N + 127) / 128;

    static cudaStream_t s2 = nullptr;
    static cudaEvent_t evF = nullptr, evJ = nullptr;
    if (s2 == nullptr) {
        cudaStreamCreateWithFlags(&s2, cudaStreamNonBlocking);
        cudaEventCreateWithFlags(&evF, cudaEventDisableTiming);
        cudaEventCreateWithFlags(&evJ, cudaEventDisableTiming);
    }

    // ---- fork: CSR build on side stream, concurrent with GEMM-1 ----
    cudaEventRecord(evF, 0);
    cudaStreamWaitEvent(s2, evF, 0);

    init_kernel<<<nB, 256, 0, s2>>>(ei);
    convert_kernel<<<eB, 256, 0, s2>>>(ei, E);
    scanA_kernel<<<nB, 256, 0, s2>>>(N);
    scanC_kernel<<<nB, 256, 0, s2>>>(N);
    fill_kernel<<<eB, 256, 0, s2>>>(E);
    cudaEventRecord(evJ, s2);

    gemm_tc_kernel<128><<<gmB, 256>>>(feature, W1, z, N);

    cudaStreamWaitEvent(0, evJ, 0);
    gather128h_kernel<<<gaB, 256>>>(z, b1, y, N);

    gemm_tc_kernel<128><<<gmB, 256>>>(y, Wh, z, N);
    gather128h_kernel<<<gaB, 256>>>(z, bh, y, N);

    gemm_tc_kernel<64><<<gmB, 256>>>(y, Wo, z, N);
    gather64h_lsm_kernel<<<gaB, 256>>>(z, bo, out, N);
}

// round 16
// speedup vs baseline: 1.4365x; 1.0135x over previous
#include <cuda_runtime.h>
#include <cuda_fp16.h>

#define N_NODES 50000
#define D 128
#define E_MAX 800000

typedef unsigned long long ull;

// ---------------- device scratch (no allocation allowed) ----------------
__device__ float  g_y[(size_t)N_NODES * D];   // gather outputs (fp32 activations)
__device__ __half g_z[(size_t)N_NODES * D];   // GEMM outputs (fp16, gathered)
__device__ int    g_is64;
__device__ int    g_src[E_MAX];
__device__ int    g_dst[E_MAX];
__device__ int    g_perm[E_MAX];              // CSR: src ids grouped by dst
__device__ int    g_deg[N_NODES];
__device__ int    g_off[N_NODES];
__device__ int    g_cur[N_NODES];
__device__ int    g_bsum[256];

// ---------------- f32x2 packed helpers ----------------
__device__ __forceinline__ ull pack2(float a, float b) {
    ull r;
    asm("mov.b64 %0, {%1, %2};" : "=l"(r) : "f"(a), "f"(b));
    return r;
}
__device__ __forceinline__ ull add2(ull a, ull b) {
    ull r;
    asm("add.rn.f32x2 %0, %1, %2;" : "=l"(r) : "l"(a), "l"(b));
    return r;
}
__device__ __forceinline__ float2 unpack2(ull v) {
    float2 r;
    asm("mov.b64 {%0, %1}, %2;" : "=f"(r.x), "=f"(r.y) : "l"(v));
    return r;
}

// accumulate 8 halves (uint4) into 4 packed f32x2 accumulators
__device__ __forceinline__ void hacc(ull& a0, ull& a1, ull& a2, ull& a3, uint4 v) {
    float2 f0 = __half22float2(*(const __half2*)&v.x);
    float2 f1 = __half22float2(*(const __half2*)&v.y);
    float2 f2 = __half22float2(*(const __half2*)&v.z);
    float2 f3 = __half22float2(*(const __half2*)&v.w);
    a0 = add2(a0, pack2(f0.x, f0.y));
    a1 = add2(a1, pack2(f1.x, f1.y));
    a2 = add2(a2, pack2(f2.x, f2.y));
    a3 = add2(a3, pack2(f3.x, f3.y));
}

// ---------------- tf32 mma helpers ----------------
__device__ __forceinline__ unsigned to_tf32(float f) {
    unsigned r;
    asm("cvt.rna.tf32.f32 %0, %1;" : "=r"(r) : "f"(f));
    return r;
}
__device__ __forceinline__ void mma_tf32(float* c, unsigned a0, unsigned a1,
                                         unsigned a2, unsigned a3,
                                         unsigned b0, unsigned b1) {
    asm volatile(
        "mma.sync.aligned.m16n8k8.row.col.f32.tf32.tf32.f32 "
        "{%0,%1,%2,%3}, {%4,%5,%6,%7}, {%8,%9}, {%0,%1,%2,%3};"
        : "+f"(c[0]), "+f"(c[1]), "+f"(c[2]), "+f"(c[3])
        : "r"(a0), "r"(a1), "r"(a2), "r"(a3), "r"(b0), "r"(b1));
}

// ---------------- init: zero degrees + dtype detect (fused) ----------------
__global__ void init_kernel(const void* __restrict__ ei) {
    int i = blockIdx.x * blockDim.x + threadIdx.x;
    if (i < N_NODES) g_deg[i] = 0;
    if (i == 0) {
        const long long* p = (const long long*)ei;
        int ok = 1;
        #pragma unroll
        for (int k = 0; k < 32; k++) {
            long long v = p[k];
            if (v < 0 || v >= N_NODES) ok = 0;
        }
        g_is64 = ok;
    }
}

// ---------------- CSR build: stage int32 + histogram (2 edges/thread) -------
__global__ void convert_kernel(const void* __restrict__ ei, int E) {
    int base = (blockIdx.x * blockDim.x + threadIdx.x) * 2;
    if (base >= E) return;
    int n = min(2, E - base);
    int s[2], d[2];
    if (g_is64) {
        const long long* p = (const long long*)ei;
        #pragma unroll
        for (int j = 0; j < 2; j++) {
            if (j < n) {
                s[j] = (int)__ldg(p + base + j);
                d[j] = (int)__ldg(p + E + base + j);
            }
        }
    } else {
        const int* p = (const int*)ei;
        #pragma unroll
        for (int j = 0; j < 2; j++) {
            if (j < n) {
                s[j] = __ldg(p + base + j);
                d[j] = __ldg(p + E + base + j);
            }
        }
    }
    #pragma unroll
    for (int j = 0; j < 2; j++) {
        if (j < n) {
            g_src[base + j] = s[j];
            g_dst[base + j] = d[j];
            atomicAdd(&g_deg[d[j]], 1);   // no return use -> RED
        }
    }
}

// per-256-block exclusive scan of deg -> off(partial), totals to bsum
__global__ void scanA_kernel(int n) {
    __shared__ int sh[8];
    int t = threadIdx.x, i = blockIdx.x * 256 + t;
    int v = (i < n) ? g_deg[i] : 0;
    int lane = t & 31, w = t >> 5;
    int x = v;
    #pragma unroll
    for (int o = 1; o < 32; o <<= 1) {
        int y = __shfl_up_sync(0xFFFFFFFFu, x, o);
        if (lane >= o) x += y;
    }
    if (lane == 31) sh[w] = x;
    __syncthreads();
    if (t < 8) {
        int s = sh[t];
        #pragma unroll
        for (int o = 1; o < 8; o <<= 1) {
            int y = __shfl_up_sync(0xFFu, s, o);
            if (t >= o) s += y;
        }
        sh[t] = s;
    }
    __syncthreads();
    int incl = x + (w ? sh[w - 1] : 0);
    if (i < n) g_off[i] = incl - v;
    if (t == 255) g_bsum[blockIdx.x] = incl;
}

// add prefix of block sums (each block reduces bsum[0..b) itself)
__global__ void scanC_kernel(int n) {
    __shared__ int wsum[8];
    int b = blockIdx.x, t = threadIdx.x;
    int s = 0;
    for (int j = t; j < b; j += 256) s += g_bsum[j];
    #pragma unroll
    for (int o = 16; o; o >>= 1) s += __shfl_xor_sync(0xFFFFFFFFu, s, o);
    if ((t & 31) == 0) wsum[t >> 5] = s;
    __syncthreads();
    int base = 0;
    #pragma unroll
    for (int w = 0; w < 8; w++) base += wsum[w];
    int i = b * 256 + t;
    if (i < n) {
        int o = g_off[i] + base;
        g_off[i] = o;
        g_cur[i] = o;
    }
}

// scatter src ids into CSR slots (4 edges/thread -> 4 atomics in flight)
__global__ void fill_kernel(int E) {
    int base = (blockIdx.x * blockDim.x + threadIdx.x) * 4;
    if (base >= E) return;
    int n = min(4, E - base);
    int d[4], s[4], pos[4];
    #pragma unroll
    for (int j = 0; j < 4; j++) {
        if (j < n) {
            d[j] = __ldg(&g_dst[base + j]);
            s[j] = __ldg(&g_src[base + j]);
        }
    }
    #pragma unroll
    for (int j = 0; j < 4; j++)
        if (j < n) pos[j] = atomicAdd(&g_cur[d[j]], 1);
    #pragma unroll
    for (int j = 0; j < 4; j++)
        if (j < n) g_perm[pos[j]] = s[j];
}

// ---------------- tf32 tensor-core GEMM: z = A @ W (fp16 out) ---------------
// R8 form: stage A+W from global each chunk; no register prefetch.
template <int C>
__global__ __launch_bounds__(256, 2)
void gemm_tc_kernel(const float* __restrict__ A,
                    const float* __restrict__ W,
                    __half* __restrict__ out,
                    int N) {
    constexpr int BM = 128;
    constexpr int BK = 32;
    constexpr int AS = BM + 8;
    constexpr int WS = C + 8;
    constexpr int NT = C / 8;
    constexpr int W4 = BK * C / 4 / 256;

    __shared__ unsigned As[BK * AS];
    __shared__ unsigned Ws[BK * WS];

    const int tid  = threadIdx.x;
    const int lane = tid & 31;
    const int warp = tid >> 5;
    const int row0 = blockIdx.x * BM;
    const int r0   = warp * 16 + (lane >> 2);
    const int kq   = lane & 3;
    const int nq   = lane >> 2;

    float acc[NT][4];
    #pragma unroll
    for (int i = 0; i < NT; i++)
        #pragma unroll
        for (int j = 0; j < 4; j++) acc[i][j] = 0.f;

    for (int kb0 = 0; kb0 < D; kb0 += BK) {
        if (kb0) __syncthreads();
        #pragma unroll
        for (int j = 0; j < 4; j++) {
            int idx = tid + j * 256;
            int r = idx & 127, c4 = idx >> 7;
            float4 v = make_float4(0.f, 0.f, 0.f, 0.f);
            if (row0 + r < N)
                v = __ldg((const float4*)(A + (size_t)(row0 + r) * D + kb0) + c4);
            As[(c4 * 4 + 0) * AS + r] = to_tf32(v.x);
            As[(c4 * 4 + 1) * AS + r] = to_tf32(v.y);
            As[(c4 * 4 + 2) * AS + r] = to_tf32(v.z);
            As[(c4 * 4 + 3) * AS + r] = to_tf32(v.w);
        }
        #pragma unroll
        for (int j = 0; j < W4; j++) {
            int idx = (tid + j * 256) * 4;
            int k = idx / C, n = idx % C;
            float4 v = __ldg((const float4*)(W + (size_t)(kb0 + k) * C + n));
            unsigned* w = &Ws[k * WS + n];
            w[0] = to_tf32(v.x);
            w[1] = to_tf32(v.y);
            w[2] = to_tf32(v.z);
            w[3] = to_tf32(v.w);
        }
        __syncthreads();

        #pragma unroll
        for (int ks = 0; ks < BK / 8; ks++) {
            int kk = ks * 8 + kq;
            unsigned a0 = As[kk * AS + r0];
            unsigned a1 = As[kk * AS + r0 + 8];
            unsigned a2 = As[(kk + 4) * AS + r0];
            unsigned a3 = As[(kk + 4) * AS + r0 + 8];
            #pragma unroll
            for (int nt = 0; nt < NT; nt++) {
                int n = nt * 8 + nq;
                unsigned b0 = Ws[kk * WS + n];
                unsigned b1 = Ws[(kk + 4) * WS + n];
                mma_tf32(acc[nt], a0, a1, a2, a3, b0, b1);
            }
        }
    }

    int rA = row0 + r0, rB = rA + 8;
    #pragma unroll
    for (int nt = 0; nt < NT; nt++) {
        int cc = nt * 8 + 2 * kq;
        if (rA < N)
            *(__half2*)(out + (size_t)rA * C + cc) = __floats2half2_rn(acc[nt][0], acc[nt][1]);
        if (rB < N)
            *(__half2*)(out + (size_t)rB * C + cc) = __floats2half2_rn(acc[nt][2], acc[nt][3]);
    }
}

// ---------- gather (128-wide, fp16 z): y[i] = relu(z[i] + sum_j z[j] + b) ---
// Warp per node, hw parity (2 neighbors/wavefront), 4 loads in flight.
__global__ void gather128h_kernel(const __half* __restrict__ z,
                                  const float* __restrict__ bias,
                                  float* __restrict__ y, int N) {
    int node = (blockIdx.x * blockDim.x + threadIdx.x) >> 5;
    int lane = threadIdx.x & 31;
    if (node >= N) return;
    const uint4* z4 = (const uint4*)z;          // 16 per row
    const int off = g_off[node];
    const int deg = g_deg[node];
    const int* __restrict__ p = g_perm + off;
    const int hw = lane >> 4;                   // 0/1: neighbor parity
    const int cg = lane & 15;                   // col group (8 halves)

    ull a0 = 0, a1 = 0, a2 = 0, a3 = 0;
    if (hw == 0)
        hacc(a0, a1, a2, a3, __ldg(z4 + (size_t)node * 16 + cg));

    int t = 0;
    for (; t + 8 <= deg; t += 8) {
        int i = t + hw;
        int s0 = __ldg(p + i),     s1 = __ldg(p + i + 2);
        int s2 = __ldg(p + i + 4), s3 = __ldg(p + i + 6);
        uint4 v0 = __ldg(z4 + (size_t)s0 * 16 + cg);
        uint4 v1 = __ldg(z4 + (size_t)s1 * 16 + cg);
        uint4 v2 = __ldg(z4 + (size_t)s2 * 16 + cg);
        uint4 v3 = __ldg(z4 + (size_t)s3 * 16 + cg);
        hacc(a0, a1, a2, a3, v0);
        hacc(a0, a1, a2, a3, v1);
        hacc(a0, a1, a2, a3, v2);
        hacc(a0, a1, a2, a3, v3);
    }
    for (; t + 2 <= deg; t += 2) {
        int s = __ldg(p + t + hw);
        hacc(a0, a1, a2, a3, __ldg(z4 + (size_t)s * 16 + cg));
    }
    if (t < deg && hw == 0) {
        int s = __ldg(p + t);
        hacc(a0, a1, a2, a3, __ldg(z4 + (size_t)s * 16 + cg));
    }

    // fold half-warps (lane l += lane l+16; same cg)
    a0 = add2(a0, __shfl_down_sync(0xFFFFFFFFu, a0, 16));
    a1 = add2(a1, __shfl_down_sync(0xFFFFFFFFu, a1, 16));
    a2 = add2(a2, __shfl_down_sync(0xFFFFFFFFu, a2, 16));
    a3 = add2(a3, __shfl_down_sync(0xFFFFFFFFu, a3, 16));

    if (hw == 0) {
        float2 f0 = unpack2(a0), f1 = unpack2(a1);
        float2 f2 = unpack2(a2), f3 = unpack2(a3);
        float4 b0 = __ldg((const float4*)bias + cg * 2);
        float4 b1 = __ldg((const float4*)bias + cg * 2 + 1);
        float4 r0, r1;
        r0.x = fmaxf(f0.x + b0.x, 0.f); r0.y = fmaxf(f0.y + b0.y, 0.f);
        r0.z = fmaxf(f1.x + b0.z, 0.f); r0.w = fmaxf(f1.y + b0.w, 0.f);
        r1.x = fmaxf(f2.x + b1.x, 0.f); r1.y = fmaxf(f2.y + b1.y, 0.f);
        r1.z = fmaxf(f3.x + b1.z, 0.f); r1.w = fmaxf(f3.y + b1.w, 0.f);
        float* o = y + (size_t)node * 128 + cg * 8;
        *(float4*)o       = r0;
        *((float4*)o + 1) = r1;
    }
}

// ---------- gather (64-wide, fp16 z) + fused log_softmax -> d_out -----------
__global__ void gather64h_lsm_kernel(const __half* __restrict__ z,
                                     const float* __restrict__ bias,
                                     float* __restrict__ out, int N) {
    int node = (blockIdx.x * blockDim.x + threadIdx.x) >> 5;
    int lane = threadIdx.x & 31;
    if (node >= N) return;
    const uint4* z4 = (const uint4*)z;          // 8 per row
    const int off = g_off[node];
    const int deg = g_deg[node];
    const int* __restrict__ p = g_perm + off;
    const int q  = lane >> 3;                   // 0..3: neighbor sub-slot
    const int cg = lane & 7;                    // col group (8 halves)

    ull a0 = 0, a1 = 0, a2 = 0, a3 = 0;
    if (q == 0)
        hacc(a0, a1, a2, a3, __ldg(z4 + (size_t)node * 8 + cg));

    int t = 0;
    for (; t + 8 <= deg; t += 8) {
        int s0 = __ldg(p + t + q), s1 = __ldg(p + t + q + 4);
        uint4 v0 = __ldg(z4 + (size_t)s0 * 8 + cg);
        uint4 v1 = __ldg(z4 + (size_t)s1 * 8 + cg);
        hacc(a0, a1, a2, a3, v0);
        hacc(a0, a1, a2, a3, v1);
    }
    for (; t + 4 <= deg; t += 4) {
        int s = __ldg(p + t + q);
        hacc(a0, a1, a2, a3, __ldg(z4 + (size_t)s * 8 + cg));
    }
    int rem = deg - t;
    if (q < rem) {
        int s = __ldg(p + t + q);
        hacc(a0, a1, a2, a3, __ldg(z4 + (size_t)s * 8 + cg));
    }

    a0 = add2(a0, __shfl_down_sync(0xFFFFFFFFu, a0, 16));
    a1 = add2(a1, __shfl_down_sync(0xFFFFFFFFu, a1, 16));
    a2 = add2(a2, __shfl_down_sync(0xFFFFFFFFu, a2, 16));
    a3 = add2(a3, __shfl_down_sync(0xFFFFFFFFu, a3, 16));
    a0 = add2(a0, __shfl_down_sync(0xFFFFFFFFu, a0, 8));
    a1 = add2(a1, __shfl_down_sync(0xFFFFFFFFu, a1, 8));
    a2 = add2(a2, __shfl_down_sync(0xFFFFFFFFu, a2, 8));
    a3 = add2(a3, __shfl_down_sync(0xFFFFFFFFu, a3, 8));

    float2 f0 = unpack2(a0), f1 = unpack2(a1);
    float2 f2 = unpack2(a2), f3 = unpack2(a3);
    float4 b0 = __ldg((const float4*)bias + cg * 2);
    float4 b1 = __ldg((const float4*)bias + cg * 2 + 1);
    float v[8];
    v[0] = f0.x + b0.x; v[1] = f0.y + b0.y; v[2] = f1.x + b0.z; v[3] = f1.y + b0.w;
    v[4] = f2.x + b1.x; v[5] = f2.y + b1.y; v[6] = f3.x + b1.z; v[7] = f3.y + b1.w;

    float m = v[0];
    #pragma unroll
    for (int j = 1; j < 8; j++) m = fmaxf(m, v[j]);
    #pragma unroll
    for (int o = 4; o; o >>= 1) m = fmaxf(m, __shfl_xor_sync(0xFFFFFFFFu, m, o));
    float s = 0.f;
    #pragma unroll
    for (int j = 0; j < 8; j++) s += expf(v[j] - m);
    #pragma unroll
    for (int o = 4; o; o >>= 1) s += __shfl_xor_sync(0xFFFFFFFFu, s, o);
    float l = m + logf(s);

    if (q == 0) {
        float* o = out + (size_t)node * 64 + cg * 8;
        *(float4*)o       = make_float4(v[0] - l, v[1] - l, v[2] - l, v[3] - l);
        *((float4*)o + 1) = make_float4(v[4] - l, v[5] - l, v[6] - l, v[7] - l);
    }
}

// ---------------- launch ----------------
extern "C" void kernel_launch(void* const* d_in, const int* in_sizes, int n_in,
                              void* d_out, int out_size) {
    const float* feature = (const float*)d_in[0];
    const void*  ei      = d_in[1];
    const float* W1      = (const float*)d_in[2];
    const float* b1      = (const float*)d_in[3];
    const float* Wh      = (const float*)d_in[4];
    const float* bh      = (const float*)d_in[5];
    const float* Wo      = (const float*)d_in[6];
    const float* bo      = (const float*)d_in[7];
    float* out = (float*)d_out;

    const int N = N_NODES;
    int E = in_sizes[1] / 2;
    if (E > E_MAX) E = E_MAX;

    float*  y;  cudaGetSymbolAddress((void**)&y, g_y);
    __half* z;  cudaGetSymbolAddress((void**)&z, g_z);

    const int nB   = (N + 255) / 256;
    const int eB2  = (E / 2 + 256) / 256;     // convert: 2 edges/thread
    const int eB4  = (E / 4 + 256) / 256;     // fill: 4 edges/thread
    const int gaB  = (N * 32 + 255) / 256;    // warp per node
    const int gmB  = (N + 127) / 128;

    static cudaStream_t s2 = nullptr;
    static cudaEvent_t evF = nullptr, evJ = nullptr;
    if (s2 == nullptr) {
        cudaStreamCreateWithFlags(&s2, cudaStreamNonBlocking);
        cudaEventCreateWithFlags(&evF, cudaEventDisableTiming);
        cudaEventCreateWithFlags(&evJ, cudaEventDisableTiming);
    }

    // ---- fork: CSR build on side stream, concurrent with GEMM-1 ----
    cudaEventRecord(evF, 0);
    cudaStreamWaitEvent(s2, evF, 0);

    init_kernel<<<nB, 256, 0, s2>>>(ei);
    convert_kernel<<<eB2, 256, 0, s2>>>(ei, E);
    scanA_kernel<<<nB, 256, 0, s2>>>(N);
    scanC_kernel<<<nB, 256, 0, s2>>>(N);
    fill_kernel<<<eB4, 256, 0, s2>>>(E);
    cudaEventRecord(evJ, s2);

    gemm_tc_kernel<128><<<gmB, 256>>>(feature, W1, z, N);

    cudaStreamWaitEvent(0, evJ, 0);
    gather128h_kernel<<<gaB, 256>>>(z, b1, y, N);

    gemm_tc_kernel<128><<<gmB, 256>>>(y, Wh, z, N);
    gather128h_kernel<<<gaB, 256>>>(z, bh, y, N);

    gemm_tc_kernel<64><<<gmB, 256>>>(y, Wo, z, N);
    gather64h_lsm_kernel<<<gaB, 256>>>(z, bo, out, N);
}

// round 17
// speedup vs baseline: 1.4385x; 1.0014x over previous
#include <cuda_runtime.h>
#include <cuda_fp16.h>

#define N_NODES 50000
#define D 128
#define E_MAX 800000

typedef unsigned long long ull;

// ---------------- PDL controls (sm_90+; no-op when not PDL-launched) --------
#define GDC_WAIT()   asm volatile("griddepcontrol.wait;" ::: "memory")
#define GDC_LAUNCH() asm volatile("griddepcontrol.launch_dependents;" ::: "memory")

// ---------------- device scratch (no allocation allowed) ----------------
__device__ float  g_y[(size_t)N_NODES * D];   // gather outputs (fp32 activations)
__device__ __half g_z[(size_t)N_NODES * D];   // GEMM outputs (fp16, gathered)
__device__ int    g_src[E_MAX];
__device__ int    g_dst[E_MAX];
__device__ int    g_perm[E_MAX];              // CSR: src ids grouped by dst
__device__ int    g_deg[N_NODES];
__device__ int    g_off[N_NODES];
__device__ int    g_cur[N_NODES];
__device__ int    g_bsum[256];

// ---------------- f32x2 packed helpers ----------------
__device__ __forceinline__ ull pack2(float a, float b) {
    ull r;
    asm("mov.b64 %0, {%1, %2};" : "=l"(r) : "f"(a), "f"(b));
    return r;
}
__device__ __forceinline__ ull add2(ull a, ull b) {
    ull r;
    asm("add.rn.f32x2 %0, %1, %2;" : "=l"(r) : "l"(a), "l"(b));
    return r;
}
__device__ __forceinline__ float2 unpack2(ull v) {
    float2 r;
    asm("mov.b64 {%0, %1}, %2;" : "=f"(r.x), "=f"(r.y) : "l"(v));
    return r;
}

// accumulate 8 halves (uint4) into 4 packed f32x2 accumulators
__device__ __forceinline__ void hacc(ull& a0, ull& a1, ull& a2, ull& a3, uint4 v) {
    float2 f0 = __half22float2(*(const __half2*)&v.x);
    float2 f1 = __half22float2(*(const __half2*)&v.y);
    float2 f2 = __half22float2(*(const __half2*)&v.z);
    float2 f3 = __half22float2(*(const __half2*)&v.w);
    a0 = add2(a0, pack2(f0.x, f0.y));
    a1 = add2(a1, pack2(f1.x, f1.y));
    a2 = add2(a2, pack2(f2.x, f2.y));
    a3 = add2(a3, pack2(f3.x, f3.y));
}

// warp-inline edge-index dtype detection (1 load + ballot; L1/L2-hot)
__device__ __forceinline__ bool detect64(const void* ei, int lane) {
    long long v = __ldg((const long long*)ei + lane);
    unsigned bad = __ballot_sync(0xFFFFFFFFu, v < 0 || v >= N_NODES);
    return bad == 0;
}

// ---------------- tf32 mma helpers ----------------
__device__ __forceinline__ unsigned to_tf32(float f) {
    unsigned r;
    asm("cvt.rna.tf32.f32 %0, %1;" : "=r"(r) : "f"(f));
    return r;
}
__device__ __forceinline__ void mma_tf32(float* c, unsigned a0, unsigned a1,
                                         unsigned a2, unsigned a3,
                                         unsigned b0, unsigned b1) {
    asm volatile(
        "mma.sync.aligned.m16n8k8.row.col.f32.tf32.tf32.f32 "
        "{%0,%1,%2,%3}, {%4,%5,%6,%7}, {%8,%9}, {%0,%1,%2,%3};"
        : "+f"(c[0]), "+f"(c[1]), "+f"(c[2]), "+f"(c[3])
        : "r"(a0), "r"(a1), "r"(a2), "r"(a3), "r"(b0), "r"(b1));
}

// ---------------- CSR build: stage int32 + histogram (2 edges/thread) -------
__global__ void convert_kernel(const void* __restrict__ ei, int E) {
    bool is64 = detect64(ei, threadIdx.x & 31);
    int base = (blockIdx.x * blockDim.x + threadIdx.x) * 2;
    if (base >= E) return;
    int n = min(2, E - base);
    int s[2], d[2];
    if (is64) {
        const long long* p = (const long long*)ei;
        #pragma unroll
        for (int j = 0; j < 2; j++) {
            if (j < n) {
                s[j] = (int)__ldg(p + base + j);
                d[j] = (int)__ldg(p + E + base + j);
            }
        }
    } else {
        const int* p = (const int*)ei;
        #pragma unroll
        for (int j = 0; j < 2; j++) {
            if (j < n) {
                s[j] = __ldg(p + base + j);
                d[j] = __ldg(p + E + base + j);
            }
        }
    }
    #pragma unroll
    for (int j = 0; j < 2; j++) {
        if (j < n) {
            g_src[base + j] = s[j];
            g_dst[base + j] = d[j];
            atomicAdd(&g_deg[d[j]], 1);
        }
    }
}

// per-256-block exclusive scan of deg -> off(partial), totals to bsum
__global__ void scanA_kernel(int n) {
    __shared__ int sh[8];
    int t = threadIdx.x, i = blockIdx.x * 256 + t;
    int v = (i < n) ? g_deg[i] : 0;
    int lane = t & 31, w = t >> 5;
    int x = v;
    #pragma unroll
    for (int o = 1; o < 32; o <<= 1) {
        int y = __shfl_up_sync(0xFFFFFFFFu, x, o);
        if (lane >= o) x += y;
    }
    if (lane == 31) sh[w] = x;
    __syncthreads();
    if (t < 8) {
        int s = sh[t];
        #pragma unroll
        for (int o = 1; o < 8; o <<= 1) {
            int y = __shfl_up_sync(0xFFu, s, o);
            if (t >= o) s += y;
        }
        sh[t] = s;
    }
    __syncthreads();
    int incl = x + (w ? sh[w - 1] : 0);
    if (i < n) g_off[i] = incl - v;
    if (t == 255) g_bsum[blockIdx.x] = incl;
}

// add prefix of block sums (each block reduces bsum[0..b) itself)
__global__ void scanC_kernel(int n) {
    __shared__ int wsum[8];
    int b = blockIdx.x, t = threadIdx.x;
    int s = 0;
    for (int j = t; j < b; j += 256) s += g_bsum[j];
    #pragma unroll
    for (int o = 16; o; o >>= 1) s += __shfl_xor_sync(0xFFFFFFFFu, s, o);
    if ((t & 31) == 0) wsum[t >> 5] = s;
    __syncthreads();
    int base = 0;
    #pragma unroll
    for (int w = 0; w < 8; w++) base += wsum[w];
    int i = b * 256 + t;
    if (i < n) {
        int o = g_off[i] + base;
        g_off[i] = o;
        g_cur[i] = o;
    }
}

// scatter src ids into CSR slots (4 edges/thread -> 4 atomics in flight)
__global__ void fill_kernel(int E) {
    int base = (blockIdx.x * blockDim.x + threadIdx.x) * 4;
    if (base >= E) return;
    int n = min(4, E - base);
    int d[4], s[4], pos[4];
    #pragma unroll
    for (int j = 0; j < 4; j++) {
        if (j < n) {
            d[j] = __ldg(&g_dst[base + j]);
            s[j] = __ldg(&g_src[base + j]);
        }
    }
    #pragma unroll
    for (int j = 0; j < 4; j++)
        if (j < n) pos[j] = atomicAdd(&g_cur[d[j]], 1);
    #pragma unroll
    for (int j = 0; j < 4; j++)
        if (j < n) g_perm[pos[j]] = s[j];
}

// ---------------- tf32 tensor-core GEMM: z = A @ W (fp16 out) ---------------
template <int C>
__global__ __launch_bounds__(256, 2)
void gemm_tc_kernel(const float* __restrict__ A,
                    const float* __restrict__ W,
                    __half* __restrict__ out,
                    int N) {
    constexpr int BM = 128;
    constexpr int BK = 32;
    constexpr int AS = BM + 8;
    constexpr int WS = C + 8;
    constexpr int NT = C / 8;
    constexpr int W4 = BK * C / 4 / 256;

    __shared__ unsigned As[BK * AS];
    __shared__ unsigned Ws[BK * WS];

    GDC_WAIT();       // predecessor's y complete (no-op when not PDL-launched)
    GDC_LAUNCH();     // allow dependents to begin scheduling

    const int tid  = threadIdx.x;
    const int lane = tid & 31;
    const int warp = tid >> 5;
    const int row0 = blockIdx.x * BM;
    const int r0   = warp * 16 + (lane >> 2);
    const int kq   = lane & 3;
    const int nq   = lane >> 2;

    float acc[NT][4];
    #pragma unroll
    for (int i = 0; i < NT; i++)
        #pragma unroll
        for (int j = 0; j < 4; j++) acc[i][j] = 0.f;

    for (int kb0 = 0; kb0 < D; kb0 += BK) {
        if (kb0) __syncthreads();
        #pragma unroll
        for (int j = 0; j < 4; j++) {
            int idx = tid + j * 256;
            int r = idx & 127, c4 = idx >> 7;
            float4 v = make_float4(0.f, 0.f, 0.f, 0.f);
            if (row0 + r < N)
                v = __ldg((const float4*)(A + (size_t)(row0 + r) * D + kb0) + c4);
            As[(c4 * 4 + 0) * AS + r] = to_tf32(v.x);
            As[(c4 * 4 + 1) * AS + r] = to_tf32(v.y);
            As[(c4 * 4 + 2) * AS + r] = to_tf32(v.z);
            As[(c4 * 4 + 3) * AS + r] = to_tf32(v.w);
        }
        #pragma unroll
        for (int j = 0; j < W4; j++) {
            int idx = (tid + j * 256) * 4;
            int k = idx / C, n = idx % C;
            float4 v = __ldg((const float4*)(W + (size_t)(kb0 + k) * C + n));
            unsigned* w = &Ws[k * WS + n];
            w[0] = to_tf32(v.x);
            w[1] = to_tf32(v.y);
            w[2] = to_tf32(v.z);
            w[3] = to_tf32(v.w);
        }
        __syncthreads();

        #pragma unroll
        for (int ks = 0; ks < BK / 8; ks++) {
            int kk = ks * 8 + kq;
            unsigned a0 = As[kk * AS + r0];
            unsigned a1 = As[kk * AS + r0 + 8];
            unsigned a2 = As[(kk + 4) * AS + r0];
            unsigned a3 = As[(kk + 4) * AS + r0 + 8];
            #pragma unroll
            for (int nt = 0; nt < NT; nt++) {
                int n = nt * 8 + nq;
                unsigned b0 = Ws[kk * WS + n];
                unsigned b1 = Ws[(kk + 4) * WS + n];
                mma_tf32(acc[nt], a0, a1, a2, a3, b0, b1);
            }
        }
    }

    int rA = row0 + r0, rB = rA + 8;
    #pragma unroll
    for (int nt = 0; nt < NT; nt++) {
        int cc = nt * 8 + 2 * kq;
        if (rA < N)
            *(__half2*)(out + (size_t)rA * C + cc) = __floats2half2_rn(acc[nt][0], acc[nt][1]);
        if (rB < N)
            *(__half2*)(out + (size_t)rB * C + cc) = __floats2half2_rn(acc[nt][2], acc[nt][3]);
    }
}

// ---------- gather (128-wide, fp16 z): y[i] = relu(z[i] + sum_j z[j] + b) ---
__global__ void gather128h_kernel(const __half* __restrict__ z,
                                  const float* __restrict__ bias,
                                  float* __restrict__ y, int N) {
    int node = (blockIdx.x * blockDim.x + threadIdx.x) >> 5;
    int lane = threadIdx.x & 31;
    if (node >= N) { GDC_WAIT(); GDC_LAUNCH(); return; }
    const int off = g_off[node];        // CSR: ready via event join, not PDL
    const int deg = g_deg[node];
    const int* __restrict__ p = g_perm + off;
    const int hw = lane >> 4;
    const int cg = lane & 15;

    GDC_WAIT();       // z from predecessor gemm complete
    GDC_LAUNCH();

    const uint4* z4 = (const uint4*)z;
    ull a0 = 0, a1 = 0, a2 = 0, a3 = 0;
    if (hw == 0)
        hacc(a0, a1, a2, a3, __ldg(z4 + (size_t)node * 16 + cg));

    int t = 0;
    for (; t + 8 <= deg; t += 8) {
        int i = t + hw;
        int s0 = __ldg(p + i),     s1 = __ldg(p + i + 2);
        int s2 = __ldg(p + i + 4), s3 = __ldg(p + i + 6);
        uint4 v0 = __ldg(z4 + (size_t)s0 * 16 + cg);
        uint4 v1 = __ldg(z4 + (size_t)s1 * 16 + cg);
        uint4 v2 = __ldg(z4 + (size_t)s2 * 16 + cg);
        uint4 v3 = __ldg(z4 + (size_t)s3 * 16 + cg);
        hacc(a0, a1, a2, a3, v0);
        hacc(a0, a1, a2, a3, v1);
        hacc(a0, a1, a2, a3, v2);
        hacc(a0, a1, a2, a3, v3);
    }
    for (; t + 2 <= deg; t += 2) {
        int s = __ldg(p + t + hw);
        hacc(a0, a1, a2, a3, __ldg(z4 + (size_t)s * 16 + cg));
    }
    if (t < deg && hw == 0) {
        int s = __ldg(p + t);
        hacc(a0, a1, a2, a3, __ldg(z4 + (size_t)s * 16 + cg));
    }

    a0 = add2(a0, __shfl_down_sync(0xFFFFFFFFu, a0, 16));
    a1 = add2(a1, __shfl_down_sync(0xFFFFFFFFu, a1, 16));
    a2 = add2(a2, __shfl_down_sync(0xFFFFFFFFu, a2, 16));
    a3 = add2(a3, __shfl_down_sync(0xFFFFFFFFu, a3, 16));

    if (hw == 0) {
        float2 f0 = unpack2(a0), f1 = unpack2(a1);
        float2 f2 = unpack2(a2), f3 = unpack2(a3);
        float4 b0 = __ldg((const float4*)bias + cg * 2);
        float4 b1 = __ldg((const float4*)bias + cg * 2 + 1);
        float4 r0, r1;
        r0.x = fmaxf(f0.x + b0.x, 0.f); r0.y = fmaxf(f0.y + b0.y, 0.f);
        r0.z = fmaxf(f1.x + b0.z, 0.f); r0.w = fmaxf(f1.y + b0.w, 0.f);
        r1.x = fmaxf(f2.x + b1.x, 0.f); r1.y = fmaxf(f2.y + b1.y, 0.f);
        r1.z = fmaxf(f3.x + b1.z, 0.f); r1.w = fmaxf(f3.y + b1.w, 0.f);
        float* o = y + (size_t)node * 128 + cg * 8;
        *(float4*)o       = r0;
        *((float4*)o + 1) = r1;
    }
}

// ---------- gather (64-wide, fp16 z) + fused log_softmax -> d_out -----------
__global__ void gather64h_lsm_kernel(const __half* __restrict__ z,
                                     const float* __restrict__ bias,
                                     float* __restrict__ out, int N) {
    int node = (blockIdx.x * blockDim.x + threadIdx.x) >> 5;
    int lane = threadIdx.x & 31;
    if (node >= N) { GDC_WAIT(); return; }
    const int off = g_off[node];
    const int deg = g_deg[node];
    const int* __restrict__ p = g_perm + off;
    const int q  = lane >> 3;
    const int cg = lane & 7;

    GDC_WAIT();       // z from gemm3 complete

    const uint4* z4 = (const uint4*)z;
    ull a0 = 0, a1 = 0, a2 = 0, a3 = 0;
    if (q == 0)
        hacc(a0, a1, a2, a3, __ldg(z4 + (size_t)node * 8 + cg));

    int t = 0;
    for (; t + 8 <= deg; t += 8) {
        int s0 = __ldg(p + t + q), s1 = __ldg(p + t + q + 4);
        uint4 v0 = __ldg(z4 + (size_t)s0 * 8 + cg);
        uint4 v1 = __ldg(z4 + (size_t)s1 * 8 + cg);
        hacc(a0, a1, a2, a3, v0);
        hacc(a0, a1, a2, a3, v1);
    }
    for (; t + 4 <= deg; t += 4) {
        int s = __ldg(p + t + q);
        hacc(a0, a1, a2, a3, __ldg(z4 + (size_t)s * 8 + cg));
    }
    int rem = deg - t;
    if (q < rem) {
        int s = __ldg(p + t + q);
        hacc(a0, a1, a2, a3, __ldg(z4 + (size_t)s * 8 + cg));
    }

    a0 = add2(a0, __shfl_down_sync(0xFFFFFFFFu, a0, 16));
    a1 = add2(a1, __shfl_down_sync(0xFFFFFFFFu, a1, 16));
    a2 = add2(a2, __shfl_down_sync(0xFFFFFFFFu, a2, 16));
    a3 = add2(a3, __shfl_down_sync(0xFFFFFFFFu, a3, 16));
    a0 = add2(a0, __shfl_down_sync(0xFFFFFFFFu, a0, 8));
    a1 = add2(a1, __shfl_down_sync(0xFFFFFFFFu, a1, 8));
    a2 = add2(a2, __shfl_down_sync(0xFFFFFFFFu, a2, 8));
    a3 = add2(a3, __shfl_down_sync(0xFFFFFFFFu, a3, 8));

    float2 f0 = unpack2(a0), f1 = unpack2(a1);
    float2 f2 = unpack2(a2), f3 = unpack2(a3);
    float4 b0 = __ldg((const float4*)bias + cg * 2);
    float4 b1 = __ldg((const float4*)bias + cg * 2 + 1);
    float v[8];
    v[0] = f0.x + b0.x; v[1] = f0.y + b0.y; v[2] = f1.x + b0.z; v[3] = f1.y + b0.w;
    v[4] = f2.x + b1.x; v[5] = f2.y + b1.y; v[6] = f3.x + b1.z; v[7] = f3.y + b1.w;

    float m = v[0];
    #pragma unroll
    for (int j = 1; j < 8; j++) m = fmaxf(m, v[j]);
    #pragma unroll
    for (int o = 4; o; o >>= 1) m = fmaxf(m, __shfl_xor_sync(0xFFFFFFFFu, m, o));
    float s = 0.f;
    #pragma unroll
    for (int j = 0; j < 8; j++) s += expf(v[j] - m);
    #pragma unroll
    for (int o = 4; o; o >>= 1) s += __shfl_xor_sync(0xFFFFFFFFu, s, o);
    float l = m + logf(s);

    if (q == 0) {
        float* o = out + (size_t)node * 64 + cg * 8;
        *(float4*)o       = make_float4(v[0] - l, v[1] - l, v[2] - l, v[3] - l);
        *((float4*)o + 1) = make_float4(v[4] - l, v[5] - l, v[6] - l, v[7] - l);
    }
}

// ---------------- PDL launch helper ----------------
static void launch_pdl(const void* func, dim3 grid, dim3 block, void** args,
                       cudaStream_t st) {
    cudaLaunchConfig_t cfg = {};
    cfg.gridDim = grid;
    cfg.blockDim = block;
    cfg.stream = st;
    cudaLaunchAttribute attr[1];
    attr[0].id = cudaLaunchAttributeProgrammaticStreamSerialization;
    attr[0].val.programmaticStreamSerializationAllowed = 1;
    cfg.attrs = attr;
    cfg.numAttrs = 1;
    cudaLaunchKernelExC(&cfg, func, args);
}

// ---------------- launch ----------------
extern "C" void kernel_launch(void* const* d_in, const int* in_sizes, int n_in,
                              void* d_out, int out_size) {
    const float* feature = (const float*)d_in[0];
    const void*  ei      = d_in[1];
    const float* W1      = (const float*)d_in[2];
    const float* b1      = (const float*)d_in[3];
    const float* Wh      = (const float*)d_in[4];
    const float* bh      = (const float*)d_in[5];
    const float* Wo      = (const float*)d_in[6];
    const float* bo      = (const float*)d_in[7];
    float* out = (float*)d_out;

    const int N = N_NODES;
    int E = in_sizes[1] / 2;
    if (E > E_MAX) E = E_MAX;

    float*  y;   cudaGetSymbolAddress((void**)&y, g_y);
    __half* z;   cudaGetSymbolAddress((void**)&z, g_z);
    int*    deg; cudaGetSymbolAddress((void**)&deg, g_deg);

    const int nB   = (N + 255) / 256;
    const int eB2  = (E / 2 + 256) / 256;     // convert: 2 edges/thread
    const int eB4  = (E / 4 + 256) / 256;     // fill: 4 edges/thread
    const int gaB  = (N * 32 + 255) / 256;    // warp per node
    const int gmB  = (N + 127) / 128;

    static cudaStream_t s2 = nullptr;
    static cudaEvent_t evF = nullptr, evJ = nullptr;
    if (s2 == nullptr) {
        cudaStreamCreateWithFlags(&s2, cudaStreamNonBlocking);
        cudaEventCreateWithFlags(&evF, cudaEventDisableTiming);
        cudaEventCreateWithFlags(&evJ, cudaEventDisableTiming);
    }

    // ---- fork: CSR build on side stream, concurrent with GEMM-1 ----
    cudaEventRecord(evF, 0);
    cudaStreamWaitEvent(s2, evF, 0);

    cudaMemsetAsync(deg, 0, N * sizeof(int), s2);
    convert_kernel<<<eB2, 256, 0, s2>>>(ei, E);
    scanA_kernel<<<nB, 256, 0, s2>>>(N);
    scanC_kernel<<<nB, 256, 0, s2>>>(N);
    fill_kernel<<<eB4, 256, 0, s2>>>(E);
    cudaEventRecord(evJ, s2);

    // gemm1: normal launch (first on main stream)
    gemm_tc_kernel<128><<<gmB, 256>>>(feature, W1, z, N);

    // join CSR, then PDL-chained layers on the main stream
    cudaStreamWaitEvent(0, evJ, 0);

    {   // gather1
        const __half* a0 = z; const float* a1 = b1; float* a2 = y; int a3 = N;
        void* args[] = { &a0, &a1, &a2, &a3 };
        launch_pdl((const void*)gather128h_kernel, dim3(gaB), dim3(256), args, 0);
    }
    {   // gemm2
        const float* a0 = y; const float* a1 = Wh; __half* a2 = z; int a3 = N;
        void* args[] = { &a0, &a1, &a2, &a3 };
        launch_pdl((const void*)gemm_tc_kernel<128>, dim3(gmB), dim3(256), args, 0);
    }
    {   // gather2
        const __half* a0 = z; const float* a1 = bh; float* a2 = y; int a3 = N;
        void* args[] = { &a0, &a1, &a2, &a3 };
        launch_pdl((const void*)gather128h_kernel, dim3(gaB), dim3(256), args, 0);
    }
    {   // gemm3
        const float* a0 = y; const float* a1 = Wo; __half* a2 = z; int a3 = N;
        void* args[] = { &a0, &a1, &a2, &a3 };
        launch_pdl((const void*)gemm_tc_kernel<64>, dim3(gmB), dim3(256), args, 0);
    }
    {   // gather3 + log_softmax
        const __half* a0 = z; const float* a1 = bo; float* a2 = out; int a3 = N;
        void* args[] = { &a0, &a1, &a2, &a3 };
        launch_pdl((const void*)gather64h_lsm_kernel, dim3(gaB), dim3(256), args, 0);
    }
}